// round 5
// baseline (speedup 1.0000x reference)
#include <cuda_runtime.h>
#include <cstdint>

// ---------------- problem constants ----------------
#define FMDIM   32
#define NPOS    1024            // 32*32
#define NANCH   9216            // 1024*9
#define NSORT   16384           // next pow2
#define NWORDS  144             // 9216/64
#define IOU_THR 0.7f
#define TOPK    300

// ---------------- scratch (static __device__, allocation-free) ----------------
__device__ float  g_col1[768 * 1024];          // im2col for backbone conv (3 MB)
__device__ float  g_feat[512 * 1024];          // backbone features          (2 MB)
__device__ float  g_col2[4608 * 1024];         // im2col for rpn conv       (18 MB)
__device__ float  g_hid [512 * 1024];          // rpn hidden                 (2 MB)
__device__ float  g_head[45 * 1024];           // rows 0..8 = cls ch 9..17, rows 9..44 = box ch 0..35
__device__ float4 g_prop[NANCH];               // decoded proposals
__device__ unsigned long long g_keys[NSORT];   // sort keys
__device__ float4 g_boxes[NANCH];              // sorted boxes
__device__ unsigned long long g_mask[(size_t)NANCH * NWORDS]; // NMS bitmask (10.6 MB)

// ---------------- im2col for backbone (16x16 stride16 VALID) ----------------
__global__ void im2col1_k(const float* __restrict__ img)
{
    int idx = blockIdx.x * blockDim.x + threadIdx.x;   // 768*1024 threads
    int k = idx >> 10, p = idx & 1023;
    int ci = k >> 8, r = k & 255, ky = r >> 4, kx = r & 15;
    int py = p >> 5, px = p & 31;
    g_col1[idx] = img[ci * 512 * 512 + (py * 16 + ky) * 512 + (px * 16 + kx)];
}

// ---------------- im2col for rpn 3x3 SAME ----------------
__global__ void im2col2_k()
{
    int idx = blockIdx.x * blockDim.x + threadIdx.x;   // 4608*1024 threads
    int k = idx >> 10, p = idx & 1023;
    int ci = k / 9, r = k - ci * 9, dy = r / 3, dx = r - dy * 3;
    int py = p >> 5, px = p & 31;
    int y = py + dy - 1, x = px + dx - 1;
    float v = 0.0f;
    if ((unsigned)y < 32u && (unsigned)x < 32u) v = g_feat[ci * 1024 + y * 32 + x];
    g_col2[idx] = v;
}

// ---------------- FP32 GEMM: C[M][1024] = A[M][K] * B[K][1024] (+bias, relu) ----------------
// 64x64 block tile, BK=16, 256 threads, 4x4 per thread, software-pipelined global loads.
__global__ void gemm_k(const float* __restrict__ A, const float* __restrict__ B,
                       float* __restrict__ C, int M, int K,
                       const float* __restrict__ bias, int relu)
{
    __shared__ float As[16][68];   // [k][m], padded to dodge store conflicts
    __shared__ float Bs[16][64];   // [k][n]

    const int bn  = blockIdx.x * 64;
    const int bm  = blockIdx.y * 64;
    const int tid = threadIdx.x;
    const int tx  = tid & 15, ty = tid >> 4;
    const int lm  = tid >> 2, lkq = (tid & 3) * 4;     // A loader: m row, k quad
    const int lkb = tid >> 4, ln4 = (tid & 15) * 4;    // B loader: k row, n quad

    float acc[4][4] = {};

    // prologue loads
    float4 av = make_float4(0.f, 0.f, 0.f, 0.f);
    if (bm + lm < M) av = *(const float4*)(A + (size_t)(bm + lm) * K + lkq);
    float4 bv = *(const float4*)(B + (size_t)lkb * 1024 + bn + ln4);

    for (int k0 = 0; k0 < K; k0 += 16) {
        As[lkq + 0][lm] = av.x; As[lkq + 1][lm] = av.y;
        As[lkq + 2][lm] = av.z; As[lkq + 3][lm] = av.w;
        *(float4*)&Bs[lkb][ln4] = bv;
        __syncthreads();

        int kn = k0 + 16;
        if (kn < K) {                                  // prefetch next tile
            av = make_float4(0.f, 0.f, 0.f, 0.f);
            if (bm + lm < M) av = *(const float4*)(A + (size_t)(bm + lm) * K + kn + lkq);
            bv = *(const float4*)(B + (size_t)(kn + lkb) * 1024 + bn + ln4);
        }

#pragma unroll
        for (int k = 0; k < 16; k++) {
            float4 a = *(const float4*)&As[k][ty * 4];
            float4 b = *(const float4*)&Bs[k][tx * 4];
            acc[0][0] += a.x * b.x; acc[0][1] += a.x * b.y; acc[0][2] += a.x * b.z; acc[0][3] += a.x * b.w;
            acc[1][0] += a.y * b.x; acc[1][1] += a.y * b.y; acc[1][2] += a.y * b.z; acc[1][3] += a.y * b.w;
            acc[2][0] += a.z * b.x; acc[2][1] += a.z * b.y; acc[2][2] += a.z * b.z; acc[2][3] += a.z * b.w;
            acc[3][0] += a.w * b.x; acc[3][1] += a.w * b.y; acc[3][2] += a.w * b.z; acc[3][3] += a.w * b.w;
        }
        __syncthreads();
    }

#pragma unroll
    for (int r = 0; r < 4; r++) {
        int m = bm + ty * 4 + r;
        if (m < M) {
            float bb = bias[m];
            float4 o = make_float4(acc[r][0] + bb, acc[r][1] + bb, acc[r][2] + bb, acc[r][3] + bb);
            if (relu) {
                o.x = fmaxf(o.x, 0.f); o.y = fmaxf(o.y, 0.f);
                o.z = fmaxf(o.z, 0.f); o.w = fmaxf(o.w, 0.f);
            }
            *(float4*)(C + (size_t)m * 1024 + bn + tx * 4) = o;
        }
    }
}

// ---------------- decode proposals + build sort keys ----------------
__global__ void decode_k(const float* __restrict__ anchors)
{
    int i = blockIdx.x * blockDim.x + threadIdx.x;     // 16384 threads
    if (i >= NANCH) { if (i < NSORT) g_keys[i] = ~0ull; return; }

    int p = i / 9, k = i - p * 9;
    float s  = g_head[k * 1024 + p];
    float d0 = g_head[(9 + k * 4 + 0) * 1024 + p];
    float d1 = g_head[(9 + k * 4 + 1) * 1024 + p];
    float d2 = g_head[(9 + k * 4 + 2) * 1024 + p];
    float d3 = g_head[(9 + k * 4 + 3) * 1024 + p];

    const float* a = anchors + (size_t)i * 4;
    float ax1 = a[0], ay1 = a[1], ax2 = a[2], ay2 = a[3];
    float wa = ax2 - ax1, ha = ay2 - ay1;
    float cxa = ax1 + 0.5f * wa, cya = ay1 + 0.5f * ha;
    float dw = fminf(fmaxf(d2, -4.f), 4.f);
    float dh = fminf(fmaxf(d3, -4.f), 4.f);
    float cx = cxa + d0 * wa, cy = cya + d1 * ha;
    float w  = wa * expf(dw), h = ha * expf(dh);
    float x1 = fmaxf(cx - 0.5f * w, 0.f);
    float y1 = fmaxf(cy - 0.5f * h, 0.f);
    float x2 = fminf(cx + 0.5f * w, 511.f);
    float y2 = fminf(cy + 0.5f * h, 511.f);
    g_prop[i] = make_float4(x1, y1, x2, y2);

    // key: score descending (stable by index ascending)
    unsigned b   = __float_as_uint(s);
    unsigned asc = (b & 0x80000000u) ? ~b : (b | 0x80000000u);
    unsigned dsc = ~asc;
    g_keys[i] = ((unsigned long long)dsc << 32) | (unsigned)i;
}

// ---------------- single-block bitonic sort of 16384 u64 keys ----------------
__global__ void sort_k()
{
    extern __shared__ unsigned long long sk[];
    int tid = threadIdx.x;
    for (int i = tid; i < NSORT; i += 1024) sk[i] = g_keys[i];
    __syncthreads();
    for (int k = 2; k <= NSORT; k <<= 1) {
        for (int j = k >> 1; j > 0; j >>= 1) {
            for (int e = tid; e < NSORT; e += 1024) {
                int ixj = e ^ j;
                if (ixj > e) {
                    unsigned long long x = sk[e], y = sk[ixj];
                    bool up = ((e & k) == 0);
                    if (up ? (x > y) : (x < y)) { sk[e] = y; sk[ixj] = x; }
                }
            }
            __syncthreads();
        }
    }
    for (int i = tid; i < NSORT; i += 1024) g_keys[i] = sk[i];
}

// ---------------- gather sorted boxes ----------------
__global__ void gather_k()
{
    int i = blockIdx.x * blockDim.x + threadIdx.x;     // 9216 threads
    if (i < NANCH) {
        int idx = (int)(g_keys[i] & 0xFFFFFFFFull);
        g_boxes[i] = g_prop[idx];
    }
}

// ---------------- NMS bitmask: mask[i][jb] bit jj set iff j>i and IoU>thr ----------------
__global__ void nms_mask_k()
{
    __shared__ float4 cb[64];
    int bxb = blockIdx.x, byb = blockIdx.y;
    int t = threadIdx.x;
    cb[t] = g_boxes[bxb * 64 + t];
    __syncthreads();

    int i = byb * 64 + t;
    unsigned long long m = 0ull;
    if (bxb >= byb) {
        float4 b  = g_boxes[i];
        float  ai = (b.z - b.x) * (b.w - b.y);
#pragma unroll 4
        for (int jj = 0; jj < 64; jj++) {
            int j = bxb * 64 + jj;
            if (j > i) {
                float4 c  = cb[jj];
                float  aj = (c.z - c.x) * (c.w - c.y);
                float iw = fmaxf(fminf(b.z, c.z) - fmaxf(b.x, c.x), 0.f);
                float ih = fmaxf(fminf(b.w, c.w) - fmaxf(b.y, c.y), 0.f);
                float inter = iw * ih;
                float iou = inter / (ai + aj - inter + 1e-9f);
                if (iou > IOU_THR) m |= (1ull << jj);
            }
        }
    }
    g_mask[(size_t)i * NWORDS + bxb] = m;
}

// ---------------- serial greedy reduce (exact reference semantics), early exit at 300 kept ----------------
__global__ void nms_reduce_k(float* __restrict__ out)
{
    __shared__ unsigned long long remv[NWORDS];
    __shared__ unsigned long long keepw[NWORDS];
    __shared__ int sel[TOPK];
    __shared__ int s_cnt, s_flag, s_done;

    int t = threadIdx.x;
    if (t < NWORDS) { remv[t] = 0ull; keepw[t] = 0ull; }
    if (t == 0) { s_cnt = 0; s_done = 0; }
    __syncthreads();

    for (int i = 0; i < NANCH; i++) {
        if (t == 0) {
            bool rm = (remv[i >> 6] >> (i & 63)) & 1ull;
            int f = 0;
            if (!rm) {
                sel[s_cnt] = i;
                s_cnt++;
                keepw[i >> 6] |= (1ull << (i & 63));
                if (s_cnt >= TOPK) s_done = 1; else f = 1;
            }
            s_flag = f;
        }
        __syncthreads();
        if (s_done) break;                       // uniform: all threads see it
        if (s_flag && t < NWORDS)
            remv[t] |= g_mask[(size_t)i * NWORDS + t];
        __syncthreads();
    }
    __syncthreads();

    // if fewer than 300 kept: stable argsort(~keep) appends suppressed in order
    if (t == 0 && s_cnt < TOPK) {
        for (int i = 0; i < NANCH && s_cnt < TOPK; i++)
            if (!((keepw[i >> 6] >> (i & 63)) & 1ull)) sel[s_cnt++] = i;
    }
    __syncthreads();

    for (int s = t; s < TOPK; s += blockDim.x) {
        float4 b = g_boxes[sel[s]];
        out[s * 4 + 0] = b.x; out[s * 4 + 1] = b.y;
        out[s * 4 + 2] = b.z; out[s * 4 + 3] = b.w;
    }
}

// ---------------- launch ----------------
extern "C" void kernel_launch(void* const* d_in, const int* in_sizes, int n_in,
                              void* d_out, int out_size)
{
    const float* img     = (const float*)d_in[0];
    const float* anchors = (const float*)d_in[1];
    const float* w_bb    = (const float*)d_in[2];
    const float* b_bb    = (const float*)d_in[3];
    const float* w_rpn   = (const float*)d_in[4];
    const float* b_rpn   = (const float*)d_in[5];
    const float* w_cls   = (const float*)d_in[6];
    const float* b_cls   = (const float*)d_in[7];
    const float* w_box   = (const float*)d_in[8];
    const float* b_box   = (const float*)d_in[9];
    float* out = (float*)d_out;

    float *col1, *feat, *col2, *hid, *head;
    cudaGetSymbolAddress((void**)&col1, g_col1);
    cudaGetSymbolAddress((void**)&feat, g_feat);
    cudaGetSymbolAddress((void**)&col2, g_col2);
    cudaGetSymbolAddress((void**)&hid,  g_hid);
    cudaGetSymbolAddress((void**)&head, g_head);

    // backbone conv: feat[512][1024] = w_bb[512][768] x col1[768][1024], relu
    im2col1_k<<<3072, 256>>>(img);
    gemm_k<<<dim3(16, 8), 256>>>(w_bb, col1, feat, 512, 768, b_bb, 1);

    // rpn conv: hid[512][1024] = w_rpn[512][4608] x col2[4608][1024], relu
    im2col2_k<<<18432, 256>>>();
    gemm_k<<<dim3(16, 8), 256>>>(w_rpn, col2, hid, 512, 4608, b_rpn, 1);

    // heads (1x1 convs): B = hid directly
    gemm_k<<<dim3(16, 1), 256>>>(w_cls + 9 * 512, hid, head,            9,  512, b_cls + 9, 0);
    gemm_k<<<dim3(16, 1), 256>>>(w_box,           hid, head + 9 * 1024, 36, 512, b_box,     0);

    // decode + keys, sort, gather
    decode_k<<<64, 256>>>(anchors);
    cudaFuncSetAttribute(sort_k, cudaFuncAttributeMaxDynamicSharedMemorySize, 131072);
    sort_k<<<1, 1024, 131072>>>();
    gather_k<<<36, 256>>>();

    // NMS
    nms_mask_k<<<dim3(NWORDS, NWORDS), 64>>>();
    nms_reduce_k<<<1, 256>>>(out);
}

// round 6
// speedup vs baseline: 1.0026x; 1.0026x over previous
#include <cuda_runtime.h>
#include <cstdint>

// ---------------- problem constants ----------------
#define FMDIM   32
#define NPOS    1024            // 32*32
#define NANCH   9216            // 1024*9
#define NSORT   16384           // next pow2
#define NWORDS  144             // 9216/64
#define IOU_THR 0.7f
#define TOPK    300

// ---------------- scratch (static __device__, allocation-free) ----------------
__device__ float  g_col1[768 * 1024];          // im2col for backbone conv (3 MB)
__device__ float  g_feat[512 * 1024];          // backbone features          (2 MB)
__device__ float  g_col2[4608 * 1024];         // im2col for rpn conv       (18 MB)
__device__ float  g_hid [512 * 1024];          // rpn hidden                 (2 MB)
__device__ float  g_head[45 * 1024];           // rows 0..8 = cls ch 9..17, rows 9..44 = box ch 0..35
__device__ float4 g_prop[NANCH];               // decoded proposals
__device__ unsigned long long g_keys[NSORT];   // sort keys
__device__ float4 g_boxes[NANCH];              // sorted boxes
__device__ unsigned long long g_mask[(size_t)NANCH * NWORDS]; // NMS bitmask (10.6 MB)

// ---------------- im2col for backbone (16x16 stride16 VALID) ----------------
__global__ void im2col1_k(const float* __restrict__ img)
{
    int idx = blockIdx.x * blockDim.x + threadIdx.x;   // 768*1024 threads
    int k = idx >> 10, p = idx & 1023;
    int ci = k >> 8, r = k & 255, ky = r >> 4, kx = r & 15;
    int py = p >> 5, px = p & 31;
    g_col1[idx] = img[ci * 512 * 512 + (py * 16 + ky) * 512 + (px * 16 + kx)];
}

// ---------------- im2col for rpn 3x3 SAME ----------------
__global__ void im2col2_k()
{
    int idx = blockIdx.x * blockDim.x + threadIdx.x;   // 4608*1024 threads
    int k = idx >> 10, p = idx & 1023;
    int ci = k / 9, r = k - ci * 9, dy = r / 3, dx = r - dy * 3;
    int py = p >> 5, px = p & 31;
    int y = py + dy - 1, x = px + dx - 1;
    float v = 0.0f;
    if ((unsigned)y < 32u && (unsigned)x < 32u) v = g_feat[ci * 1024 + y * 32 + x];
    g_col2[idx] = v;
}

// ---------------- FP32 GEMM: C[M][1024] = A[M][K] * B[K][1024] (+bias, relu) ----------------
// 64x64 block tile, BK=16, 256 threads, 4x4 per thread, software-pipelined global loads.
__global__ void gemm_k(const float* __restrict__ A, const float* __restrict__ B,
                       float* __restrict__ C, int M, int K,
                       const float* __restrict__ bias, int relu)
{
    __shared__ float As[16][68];   // [k][m], padded to dodge store conflicts
    __shared__ float Bs[16][64];   // [k][n]

    const int bn  = blockIdx.x * 64;
    const int bm  = blockIdx.y * 64;
    const int tid = threadIdx.x;
    const int tx  = tid & 15, ty = tid >> 4;
    const int lm  = tid >> 2, lkq = (tid & 3) * 4;     // A loader: m row, k quad
    const int lkb = tid >> 4, ln4 = (tid & 15) * 4;    // B loader: k row, n quad

    float acc[4][4] = {};

    // prologue loads
    float4 av = make_float4(0.f, 0.f, 0.f, 0.f);
    if (bm + lm < M) av = *(const float4*)(A + (size_t)(bm + lm) * K + lkq);
    float4 bv = *(const float4*)(B + (size_t)lkb * 1024 + bn + ln4);

    for (int k0 = 0; k0 < K; k0 += 16) {
        As[lkq + 0][lm] = av.x; As[lkq + 1][lm] = av.y;
        As[lkq + 2][lm] = av.z; As[lkq + 3][lm] = av.w;
        *(float4*)&Bs[lkb][ln4] = bv;
        __syncthreads();

        int kn = k0 + 16;
        if (kn < K) {                                  // prefetch next tile
            av = make_float4(0.f, 0.f, 0.f, 0.f);
            if (bm + lm < M) av = *(const float4*)(A + (size_t)(bm + lm) * K + kn + lkq);
            bv = *(const float4*)(B + (size_t)(kn + lkb) * 1024 + bn + ln4);
        }

#pragma unroll
        for (int k = 0; k < 16; k++) {
            float4 a = *(const float4*)&As[k][ty * 4];
            float4 b = *(const float4*)&Bs[k][tx * 4];
            acc[0][0] += a.x * b.x; acc[0][1] += a.x * b.y; acc[0][2] += a.x * b.z; acc[0][3] += a.x * b.w;
            acc[1][0] += a.y * b.x; acc[1][1] += a.y * b.y; acc[1][2] += a.y * b.z; acc[1][3] += a.y * b.w;
            acc[2][0] += a.z * b.x; acc[2][1] += a.z * b.y; acc[2][2] += a.z * b.z; acc[2][3] += a.z * b.w;
            acc[3][0] += a.w * b.x; acc[3][1] += a.w * b.y; acc[3][2] += a.w * b.z; acc[3][3] += a.w * b.w;
        }
        __syncthreads();
    }

#pragma unroll
    for (int r = 0; r < 4; r++) {
        int m = bm + ty * 4 + r;
        if (m < M) {
            float bb = bias[m];
            float4 o = make_float4(acc[r][0] + bb, acc[r][1] + bb, acc[r][2] + bb, acc[r][3] + bb);
            if (relu) {
                o.x = fmaxf(o.x, 0.f); o.y = fmaxf(o.y, 0.f);
                o.z = fmaxf(o.z, 0.f); o.w = fmaxf(o.w, 0.f);
            }
            *(float4*)(C + (size_t)m * 1024 + bn + tx * 4) = o;
        }
    }
}

// ---------------- decode proposals + build sort keys ----------------
__global__ void decode_k(const float* __restrict__ anchors)
{
    int i = blockIdx.x * blockDim.x + threadIdx.x;     // 16384 threads
    if (i >= NANCH) { if (i < NSORT) g_keys[i] = ~0ull; return; }

    int p = i / 9, k = i - p * 9;
    float s  = g_head[k * 1024 + p];
    float d0 = g_head[(9 + k * 4 + 0) * 1024 + p];
    float d1 = g_head[(9 + k * 4 + 1) * 1024 + p];
    float d2 = g_head[(9 + k * 4 + 2) * 1024 + p];
    float d3 = g_head[(9 + k * 4 + 3) * 1024 + p];

    const float* a = anchors + (size_t)i * 4;
    float ax1 = a[0], ay1 = a[1], ax2 = a[2], ay2 = a[3];
    float wa = ax2 - ax1, ha = ay2 - ay1;
    float cxa = ax1 + 0.5f * wa, cya = ay1 + 0.5f * ha;
    float dw = fminf(fmaxf(d2, -4.f), 4.f);
    float dh = fminf(fmaxf(d3, -4.f), 4.f);
    float cx = cxa + d0 * wa, cy = cya + d1 * ha;
    float w  = wa * expf(dw), h = ha * expf(dh);
    float x1 = fmaxf(cx - 0.5f * w, 0.f);
    float y1 = fmaxf(cy - 0.5f * h, 0.f);
    float x2 = fminf(cx + 0.5f * w, 511.f);
    float y2 = fminf(cy + 0.5f * h, 511.f);
    g_prop[i] = make_float4(x1, y1, x2, y2);

    // key: score descending (stable by index ascending)
    unsigned b   = __float_as_uint(s);
    unsigned asc = (b & 0x80000000u) ? ~b : (b | 0x80000000u);
    unsigned dsc = ~asc;
    g_keys[i] = ((unsigned long long)dsc << 32) | (unsigned)i;
}

// ---------------- single-block bitonic sort of 16384 u64 keys ----------------
__global__ void sort_k()
{
    extern __shared__ unsigned long long sk[];
    int tid = threadIdx.x;
    for (int i = tid; i < NSORT; i += 1024) sk[i] = g_keys[i];
    __syncthreads();
    for (int k = 2; k <= NSORT; k <<= 1) {
        for (int j = k >> 1; j > 0; j >>= 1) {
            for (int e = tid; e < NSORT; e += 1024) {
                int ixj = e ^ j;
                if (ixj > e) {
                    unsigned long long x = sk[e], y = sk[ixj];
                    bool up = ((e & k) == 0);
                    if (up ? (x > y) : (x < y)) { sk[e] = y; sk[ixj] = x; }
                }
            }
            __syncthreads();
        }
    }
    for (int i = tid; i < NSORT; i += 1024) g_keys[i] = sk[i];
}

// ---------------- gather sorted boxes ----------------
__global__ void gather_k()
{
    int i = blockIdx.x * blockDim.x + threadIdx.x;     // 9216 threads
    if (i < NANCH) {
        int idx = (int)(g_keys[i] & 0xFFFFFFFFull);
        g_boxes[i] = g_prop[idx];
    }
}

// ---------------- NMS bitmask: mask[i][jb] bit jj set iff j>i and IoU>thr ----------------
__global__ void nms_mask_k()
{
    __shared__ float4 cb[64];
    int bxb = blockIdx.x, byb = blockIdx.y;
    int t = threadIdx.x;
    cb[t] = g_boxes[bxb * 64 + t];
    __syncthreads();

    int i = byb * 64 + t;
    unsigned long long m = 0ull;
    if (bxb >= byb) {
        float4 b  = g_boxes[i];
        float  ai = (b.z - b.x) * (b.w - b.y);
#pragma unroll 4
        for (int jj = 0; jj < 64; jj++) {
            int j = bxb * 64 + jj;
            if (j > i) {
                float4 c  = cb[jj];
                float  aj = (c.z - c.x) * (c.w - c.y);
                float iw = fmaxf(fminf(b.z, c.z) - fmaxf(b.x, c.x), 0.f);
                float ih = fmaxf(fminf(b.w, c.w) - fmaxf(b.y, c.y), 0.f);
                float inter = iw * ih;
                float iou = inter / (ai + aj - inter + 1e-9f);
                if (iou > IOU_THR) m |= (1ull << jj);
            }
        }
    }
    g_mask[(size_t)i * NWORDS + bxb] = m;
}

// ---------------- serial greedy reduce (exact reference semantics), early exit at 300 kept ----------------
__global__ void nms_reduce_k(float* __restrict__ out)
{
    __shared__ unsigned long long remv[NWORDS];
    __shared__ unsigned long long keepw[NWORDS];
    __shared__ int sel[TOPK];
    __shared__ int s_cnt, s_flag, s_done;

    int t = threadIdx.x;
    if (t < NWORDS) { remv[t] = 0ull; keepw[t] = 0ull; }
    if (t == 0) { s_cnt = 0; s_done = 0; }
    __syncthreads();

    for (int i = 0; i < NANCH; i++) {
        if (t == 0) {
            bool rm = (remv[i >> 6] >> (i & 63)) & 1ull;
            int f = 0;
            if (!rm) {
                sel[s_cnt] = i;
                s_cnt++;
                keepw[i >> 6] |= (1ull << (i & 63));
                if (s_cnt >= TOPK) s_done = 1; else f = 1;
            }
            s_flag = f;
        }
        __syncthreads();
        if (s_done) break;                       // uniform: all threads see it
        if (s_flag && t < NWORDS)
            remv[t] |= g_mask[(size_t)i * NWORDS + t];
        __syncthreads();
    }
    __syncthreads();

    // if fewer than 300 kept: stable argsort(~keep) appends suppressed in order
    if (t == 0 && s_cnt < TOPK) {
        for (int i = 0; i < NANCH && s_cnt < TOPK; i++)
            if (!((keepw[i >> 6] >> (i & 63)) & 1ull)) sel[s_cnt++] = i;
    }
    __syncthreads();

    for (int s = t; s < TOPK; s += blockDim.x) {
        float4 b = g_boxes[sel[s]];
        out[s * 4 + 0] = b.x; out[s * 4 + 1] = b.y;
        out[s * 4 + 2] = b.z; out[s * 4 + 3] = b.w;
    }
}

// ---------------- launch ----------------
extern "C" void kernel_launch(void* const* d_in, const int* in_sizes, int n_in,
                              void* d_out, int out_size)
{
    const float* img     = (const float*)d_in[0];
    const float* anchors = (const float*)d_in[1];
    const float* w_bb    = (const float*)d_in[2];
    const float* b_bb    = (const float*)d_in[3];
    const float* w_rpn   = (const float*)d_in[4];
    const float* b_rpn   = (const float*)d_in[5];
    const float* w_cls   = (const float*)d_in[6];
    const float* b_cls   = (const float*)d_in[7];
    const float* w_box   = (const float*)d_in[8];
    const float* b_box   = (const float*)d_in[9];
    float* out = (float*)d_out;

    float *col1, *feat, *col2, *hid, *head;
    cudaGetSymbolAddress((void**)&col1, g_col1);
    cudaGetSymbolAddress((void**)&feat, g_feat);
    cudaGetSymbolAddress((void**)&col2, g_col2);
    cudaGetSymbolAddress((void**)&hid,  g_hid);
    cudaGetSymbolAddress((void**)&head, g_head);

    // backbone conv: feat[512][1024] = w_bb[512][768] x col1[768][1024], relu
    im2col1_k<<<3072, 256>>>(img);
    gemm_k<<<dim3(16, 8), 256>>>(w_bb, col1, feat, 512, 768, b_bb, 1);

    // rpn conv: hid[512][1024] = w_rpn[512][4608] x col2[4608][1024], relu
    im2col2_k<<<18432, 256>>>();
    gemm_k<<<dim3(16, 8), 256>>>(w_rpn, col2, hid, 512, 4608, b_rpn, 1);

    // heads (1x1 convs): B = hid directly
    gemm_k<<<dim3(16, 1), 256>>>(w_cls + 9 * 512, hid, head,            9,  512, b_cls + 9, 0);
    gemm_k<<<dim3(16, 1), 256>>>(w_box,           hid, head + 9 * 1024, 36, 512, b_box,     0);

    // decode + keys, sort, gather
    decode_k<<<64, 256>>>(anchors);
    cudaFuncSetAttribute(sort_k, cudaFuncAttributeMaxDynamicSharedMemorySize, 131072);
    sort_k<<<1, 1024, 131072>>>();
    gather_k<<<36, 256>>>();

    // NMS
    nms_mask_k<<<dim3(NWORDS, NWORDS), 64>>>();
    nms_reduce_k<<<1, 256>>>(out);
}

// round 7
// speedup vs baseline: 1.6570x; 1.6528x over previous
#include <cuda_runtime.h>
#include <cstdint>

// ---------------- problem constants ----------------
#define FMDIM   32
#define NPOS    1024            // 32*32
#define NANCH   9216            // 1024*9
#define NSORT   16384           // next pow2
#define NWORDS  144             // 9216/64
#define IOU_THR 0.7f
#define TOPK    300

// ---------------- scratch (static __device__, allocation-free) ----------------
__device__ float  g_col1[768 * 1024];          // im2col backbone        (3 MB)
__device__ float  g_feat[512 * 1024];          // backbone features      (2 MB)
__device__ float  g_col2[4608 * 1024];         // im2col rpn            (18 MB)
__device__ float  g_hid [512 * 1024];          // rpn hidden             (2 MB)
__device__ float  g_part[8 * 512 * 1024];      // split-K partials      (16 MB)
__device__ float  g_head[45 * 1024];           // rows 0..8 cls ch9..17, 9..44 box
__device__ float4 g_prop[NANCH];
__device__ unsigned long long g_keys [NSORT];
__device__ unsigned long long g_keys2[NSORT];
__device__ float4 g_boxes[NANCH];
__device__ unsigned long long g_mask[(size_t)NANCH * NWORDS]; // 10.6 MB

// ---------------- im2col for backbone (16x16 stride16 VALID) ----------------
__global__ void im2col1_k(const float* __restrict__ img)
{
    int idx = blockIdx.x * blockDim.x + threadIdx.x;   // 768*1024 threads
    int k = idx >> 10, p = idx & 1023;
    int ci = k >> 8, r = k & 255, ky = r >> 4, kx = r & 15;
    int py = p >> 5, px = p & 31;
    g_col1[idx] = img[ci * 512 * 512 + (py * 16 + ky) * 512 + (px * 16 + kx)];
}

// ---------------- im2col for rpn 3x3 SAME ----------------
__global__ void im2col2_k()
{
    int idx = blockIdx.x * blockDim.x + threadIdx.x;   // 4608*1024 threads
    int k = idx >> 10, p = idx & 1023;
    int ci = k / 9, r = k - ci * 9, dy = r / 3, dx = r - dy * 3;
    int py = p >> 5, px = p & 31;
    int y = py + dy - 1, x = px + dx - 1;
    float v = 0.0f;
    if ((unsigned)y < 32u && (unsigned)x < 32u) v = g_feat[ci * 1024 + y * 32 + x];
    g_col2[idx] = v;
}

// ---------------- split-K FP32 GEMM: P[s] += A[0:512][K] x B[K][1024] ----------------
// 128x128 tile, BK=8, 256 threads, 8x8 micro (4+4 split). M=512, N=1024 exact.
__global__ void gemm128_k(const float* __restrict__ A, const float* __restrict__ B,
                          float* __restrict__ P, int Ktot, int ksplit)
{
    __shared__ float As[8][132];   // [k][m], 132 pad -> conflict-free scatter store
    __shared__ float Bs[8][128];   // [k][n]

    const int bn = blockIdx.x * 128;
    const int bm = blockIdx.y * 128;
    const int s  = blockIdx.z;
    const int kbase = s * ksplit;
    const int tid = threadIdx.x;
    const int tx = tid & 15, ty = tid >> 4;
    const int alm = tid >> 1, alk = (tid & 1) * 4;     // A loader
    const int blk = tid >> 5, bln = (tid & 31) * 4;    // B loader

    const float* Aptr = A + (size_t)(bm + alm) * Ktot + kbase + alk;
    const float* Bptr = B + (size_t)(kbase + blk) * 1024 + bn + bln;

    float acc[8][8] = {};

    float4 av = *(const float4*)Aptr;
    float4 bv = *(const float4*)Bptr;

    for (int k0 = 0; k0 < ksplit; k0 += 8) {
        As[alk + 0][alm] = av.x; As[alk + 1][alm] = av.y;
        As[alk + 2][alm] = av.z; As[alk + 3][alm] = av.w;
        *(float4*)&Bs[blk][bln] = bv;
        __syncthreads();

        if (k0 + 8 < ksplit) {                         // prefetch next tile
            av = *(const float4*)(Aptr + k0 + 8);
            bv = *(const float4*)(Bptr + (size_t)(k0 + 8) * 1024);
        }

#pragma unroll
        for (int k = 0; k < 8; k++) {
            float4 a0 = *(const float4*)&As[k][ty * 4];
            float4 a1 = *(const float4*)&As[k][ty * 4 + 64];
            float4 b0 = *(const float4*)&Bs[k][tx * 4];
            float4 b1 = *(const float4*)&Bs[k][tx * 4 + 64];
            float a[8] = {a0.x, a0.y, a0.z, a0.w, a1.x, a1.y, a1.z, a1.w};
            float b[8] = {b0.x, b0.y, b0.z, b0.w, b1.x, b1.y, b1.z, b1.w};
#pragma unroll
            for (int i = 0; i < 8; i++)
#pragma unroll
                for (int j = 0; j < 8; j++)
                    acc[i][j] += a[i] * b[j];
        }
        __syncthreads();
    }

    float* Pp = P + (size_t)s * 512 * 1024;
#pragma unroll
    for (int ih = 0; ih < 2; ih++)
#pragma unroll
        for (int r = 0; r < 4; r++) {
            int i = ih * 4 + r;
            int m = bm + ih * 64 + ty * 4 + r;
            float4 o0 = make_float4(acc[i][0], acc[i][1], acc[i][2], acc[i][3]);
            float4 o1 = make_float4(acc[i][4], acc[i][5], acc[i][6], acc[i][7]);
            *(float4*)(Pp + (size_t)m * 1024 + bn + tx * 4)      = o0;
            *(float4*)(Pp + (size_t)m * 1024 + bn + tx * 4 + 64) = o1;
        }
}

// ---------------- deterministic split-K reduce (+bias+relu) ----------------
__global__ void reduce_k(const float* __restrict__ P, float* __restrict__ C,
                         const float* __restrict__ bias, int S, int relu)
{
    int idx = blockIdx.x * blockDim.x + threadIdx.x;   // 131072 threads (float4)
    int m = idx >> 8, n4 = (idx & 255) * 4;
    float4 acc = make_float4(0.f, 0.f, 0.f, 0.f);
    for (int s = 0; s < S; s++) {                      // fixed order
        float4 v = *(const float4*)(P + ((size_t)s * 512 + m) * 1024 + n4);
        acc.x += v.x; acc.y += v.y; acc.z += v.z; acc.w += v.w;
    }
    float bb = bias[m];
    acc.x += bb; acc.y += bb; acc.z += bb; acc.w += bb;
    if (relu) {
        acc.x = fmaxf(acc.x, 0.f); acc.y = fmaxf(acc.y, 0.f);
        acc.z = fmaxf(acc.z, 0.f); acc.w = fmaxf(acc.w, 0.f);
    }
    *(float4*)(C + (size_t)m * 1024 + n4) = acc;
}

// ---------------- small GEMM for heads (M<=64): C[M][1024]=A[M][K]xB ----------------
__global__ void gemm_k(const float* __restrict__ A, const float* __restrict__ B,
                       float* __restrict__ C, int M, int K,
                       const float* __restrict__ bias, int relu)
{
    __shared__ float As[16][68];
    __shared__ float Bs[16][64];

    const int bn  = blockIdx.x * 64;
    const int bm  = blockIdx.y * 64;
    const int tid = threadIdx.x;
    const int tx  = tid & 15, ty = tid >> 4;
    const int lm  = tid >> 2, lkq = (tid & 3) * 4;
    const int lkb = tid >> 4, ln4 = (tid & 15) * 4;

    float acc[4][4] = {};

    float4 av = make_float4(0.f, 0.f, 0.f, 0.f);
    if (bm + lm < M) av = *(const float4*)(A + (size_t)(bm + lm) * K + lkq);
    float4 bv = *(const float4*)(B + (size_t)lkb * 1024 + bn + ln4);

    for (int k0 = 0; k0 < K; k0 += 16) {
        As[lkq + 0][lm] = av.x; As[lkq + 1][lm] = av.y;
        As[lkq + 2][lm] = av.z; As[lkq + 3][lm] = av.w;
        *(float4*)&Bs[lkb][ln4] = bv;
        __syncthreads();

        int kn = k0 + 16;
        if (kn < K) {
            av = make_float4(0.f, 0.f, 0.f, 0.f);
            if (bm + lm < M) av = *(const float4*)(A + (size_t)(bm + lm) * K + kn + lkq);
            bv = *(const float4*)(B + (size_t)(kn + lkb) * 1024 + bn + ln4);
        }

#pragma unroll
        for (int k = 0; k < 16; k++) {
            float4 a = *(const float4*)&As[k][ty * 4];
            float4 b = *(const float4*)&Bs[k][tx * 4];
            acc[0][0] += a.x * b.x; acc[0][1] += a.x * b.y; acc[0][2] += a.x * b.z; acc[0][3] += a.x * b.w;
            acc[1][0] += a.y * b.x; acc[1][1] += a.y * b.y; acc[1][2] += a.y * b.z; acc[1][3] += a.y * b.w;
            acc[2][0] += a.z * b.x; acc[2][1] += a.z * b.y; acc[2][2] += a.z * b.z; acc[2][3] += a.z * b.w;
            acc[3][0] += a.w * b.x; acc[3][1] += a.w * b.y; acc[3][2] += a.w * b.z; acc[3][3] += a.w * b.w;
        }
        __syncthreads();
    }

#pragma unroll
    for (int r = 0; r < 4; r++) {
        int m = bm + ty * 4 + r;
        if (m < M) {
            float bb = bias[m];
            float4 o = make_float4(acc[r][0] + bb, acc[r][1] + bb, acc[r][2] + bb, acc[r][3] + bb);
            if (relu) {
                o.x = fmaxf(o.x, 0.f); o.y = fmaxf(o.y, 0.f);
                o.z = fmaxf(o.z, 0.f); o.w = fmaxf(o.w, 0.f);
            }
            *(float4*)(C + (size_t)m * 1024 + bn + tx * 4) = o;
        }
    }
}

// ---------------- decode proposals + build sort keys (unique keys) ----------------
__global__ void decode_k(const float* __restrict__ anchors)
{
    int i = blockIdx.x * blockDim.x + threadIdx.x;     // 16384 threads
    if (i >= NANCH) {
        if (i < NSORT) g_keys[i] = (0xFFFFFFFFull << 32) | (unsigned)i;  // unique pad
        return;
    }

    int p = i / 9, k = i - p * 9;
    float s  = g_head[k * 1024 + p];
    float d0 = g_head[(9 + k * 4 + 0) * 1024 + p];
    float d1 = g_head[(9 + k * 4 + 1) * 1024 + p];
    float d2 = g_head[(9 + k * 4 + 2) * 1024 + p];
    float d3 = g_head[(9 + k * 4 + 3) * 1024 + p];

    const float* a = anchors + (size_t)i * 4;
    float ax1 = a[0], ay1 = a[1], ax2 = a[2], ay2 = a[3];
    float wa = ax2 - ax1, ha = ay2 - ay1;
    float cxa = ax1 + 0.5f * wa, cya = ay1 + 0.5f * ha;
    float dw = fminf(fmaxf(d2, -4.f), 4.f);
    float dh = fminf(fmaxf(d3, -4.f), 4.f);
    float cx = cxa + d0 * wa, cy = cya + d1 * ha;
    float w  = wa * expf(dw), h = ha * expf(dh);
    float x1 = fmaxf(cx - 0.5f * w, 0.f);
    float y1 = fmaxf(cy - 0.5f * h, 0.f);
    float x2 = fminf(cx + 0.5f * w, 511.f);
    float y2 = fminf(cy + 0.5f * h, 511.f);
    g_prop[i] = make_float4(x1, y1, x2, y2);

    unsigned b   = __float_as_uint(s);
    unsigned asc = (b & 0x80000000u) ? ~b : (b | 0x80000000u);
    unsigned dsc = ~asc;
    g_keys[i] = ((unsigned long long)dsc << 32) | (unsigned)i;
}

// ---------------- stage A: 16 blocks each bitonic-sort 1024 keys ----------------
__global__ void sort1_k()
{
    __shared__ unsigned long long sk[1024];
    int base = blockIdx.x << 10, t = threadIdx.x;      // 512 threads
    sk[t]       = g_keys[base + t];
    sk[t + 512] = g_keys[base + t + 512];
    __syncthreads();
    for (int k = 2; k <= 1024; k <<= 1) {
        for (int j = k >> 1; j > 0; j >>= 1) {
            for (int e = t; e < 1024; e += 512) {
                int ixj = e ^ j;
                if (ixj > e) {
                    unsigned long long x = sk[e], y = sk[ixj];
                    bool up = ((e & k) == 0);
                    if (up ? (x > y) : (x < y)) { sk[e] = y; sk[ixj] = x; }
                }
            }
            __syncthreads();
        }
    }
    g_keys[base + t]       = sk[t];
    g_keys[base + t + 512] = sk[t + 512];
}

// ---------------- stage B: rank-merge pairs of sorted runs of length L ----------------
__global__ void merge_k(const unsigned long long* __restrict__ src,
                        unsigned long long* __restrict__ dst, int L)
{
    int i = blockIdx.x * blockDim.x + threadIdx.x;     // 16384 threads
    int pair = i / (2 * L);
    int base = pair * 2 * L;
    int r = i - base;
    unsigned long long v;
    const unsigned long long* other;
    int myidx;
    if (r < L) { v = src[base + r];     other = src + base + L; myidx = r; }
    else       { v = src[base + r];     other = src + base;     myidx = r - L; }
    int lo = 0, hi = L;                                // count other < v (keys unique)
    while (lo < hi) {
        int mid = (lo + hi) >> 1;
        if (other[mid] < v) lo = mid + 1; else hi = mid;
    }
    dst[base + myidx + lo] = v;
}

// ---------------- gather sorted boxes ----------------
__global__ void gather_k()
{
    int i = blockIdx.x * blockDim.x + threadIdx.x;
    if (i < NANCH) {
        int idx = (int)(g_keys[i] & 0xFFFFFFFFull);
        g_boxes[i] = g_prop[idx];
    }
}

// ---------------- NMS bitmask ----------------
__global__ void nms_mask_k()
{
    __shared__ float4 cb[64];
    int bxb = blockIdx.x, byb = blockIdx.y;
    int t = threadIdx.x;
    cb[t] = g_boxes[bxb * 64 + t];
    __syncthreads();

    int i = byb * 64 + t;
    unsigned long long m = 0ull;
    if (bxb >= byb) {
        float4 b  = g_boxes[i];
        float  ai = (b.z - b.x) * (b.w - b.y);
#pragma unroll 4
        for (int jj = 0; jj < 64; jj++) {
            int j = bxb * 64 + jj;
            if (j > i) {
                float4 c  = cb[jj];
                float  aj = (c.z - c.x) * (c.w - c.y);
                float iw = fmaxf(fminf(b.z, c.z) - fmaxf(b.x, c.x), 0.f);
                float ih = fmaxf(fminf(b.w, c.w) - fmaxf(b.y, c.y), 0.f);
                float inter = iw * ih;
                float iou = inter / (ai + aj - inter + 1e-9f);
                if (iou > IOU_THR) m |= (1ull << jj);
            }
        }
    }
    g_mask[(size_t)i * NWORDS + bxb] = m;
}

// ---------------- serial greedy reduce, early exit at 300 kept ----------------
__global__ void nms_reduce_k(float* __restrict__ out)
{
    __shared__ unsigned long long remv[NWORDS];
    __shared__ unsigned long long keepw[NWORDS];
    __shared__ int sel[TOPK];
    __shared__ int s_cnt, s_flag, s_done;

    int t = threadIdx.x;
    if (t < NWORDS) { remv[t] = 0ull; keepw[t] = 0ull; }
    if (t == 0) { s_cnt = 0; s_done = 0; }
    __syncthreads();

    for (int i = 0; i < NANCH; i++) {
        if (t == 0) {
            bool rm = (remv[i >> 6] >> (i & 63)) & 1ull;
            int f = 0;
            if (!rm) {
                sel[s_cnt] = i;
                s_cnt++;
                keepw[i >> 6] |= (1ull << (i & 63));
                if (s_cnt >= TOPK) s_done = 1; else f = 1;
            }
            s_flag = f;
        }
        __syncthreads();
        if (s_done) break;
        if (s_flag && t < NWORDS)
            remv[t] |= g_mask[(size_t)i * NWORDS + t];
        __syncthreads();
    }
    __syncthreads();

    if (t == 0 && s_cnt < TOPK) {
        for (int i = 0; i < NANCH && s_cnt < TOPK; i++)
            if (!((keepw[i >> 6] >> (i & 63)) & 1ull)) sel[s_cnt++] = i;
    }
    __syncthreads();

    for (int s = t; s < TOPK; s += blockDim.x) {
        float4 b = g_boxes[sel[s]];
        out[s * 4 + 0] = b.x; out[s * 4 + 1] = b.y;
        out[s * 4 + 2] = b.z; out[s * 4 + 3] = b.w;
    }
}

// ---------------- launch ----------------
extern "C" void kernel_launch(void* const* d_in, const int* in_sizes, int n_in,
                              void* d_out, int out_size)
{
    const float* img     = (const float*)d_in[0];
    const float* anchors = (const float*)d_in[1];
    const float* w_bb    = (const float*)d_in[2];
    const float* b_bb    = (const float*)d_in[3];
    const float* w_rpn   = (const float*)d_in[4];
    const float* b_rpn   = (const float*)d_in[5];
    const float* w_cls   = (const float*)d_in[6];
    const float* b_cls   = (const float*)d_in[7];
    const float* w_box   = (const float*)d_in[8];
    const float* b_box   = (const float*)d_in[9];
    float* out = (float*)d_out;

    float *col1, *feat, *col2, *hid, *head, *part;
    unsigned long long *keys, *keys2;
    cudaGetSymbolAddress((void**)&col1,  g_col1);
    cudaGetSymbolAddress((void**)&feat,  g_feat);
    cudaGetSymbolAddress((void**)&col2,  g_col2);
    cudaGetSymbolAddress((void**)&hid,   g_hid);
    cudaGetSymbolAddress((void**)&head,  g_head);
    cudaGetSymbolAddress((void**)&part,  g_part);
    cudaGetSymbolAddress((void**)&keys,  g_keys);
    cudaGetSymbolAddress((void**)&keys2, g_keys2);

    // backbone conv: split-K 4 (K=768, ksplit=192)
    im2col1_k<<<3072, 256>>>(img);
    gemm128_k<<<dim3(8, 4, 4), 256>>>(w_bb, col1, part, 768, 192);
    reduce_k<<<512, 256>>>(part, feat, b_bb, 4, 1);

    // rpn conv: split-K 8 (K=4608, ksplit=576)
    im2col2_k<<<18432, 256>>>();
    gemm128_k<<<dim3(8, 4, 8), 256>>>(w_rpn, col2, part, 4608, 576);
    reduce_k<<<512, 256>>>(part, hid, b_rpn, 8, 1);

    // heads (1x1 convs)
    gemm_k<<<dim3(16, 1), 256>>>(w_cls + 9 * 512, hid, head,            9,  512, b_cls + 9, 0);
    gemm_k<<<dim3(16, 1), 256>>>(w_box,           hid, head + 9 * 1024, 36, 512, b_box,     0);

    // decode + keys
    decode_k<<<64, 256>>>(anchors);

    // sort: 16 local bitonic sorts, then 4 rank-merge rounds
    sort1_k<<<16, 512>>>();
    merge_k<<<64, 256>>>(keys,  keys2, 1024);
    merge_k<<<64, 256>>>(keys2, keys,  2048);
    merge_k<<<64, 256>>>(keys,  keys2, 4096);
    merge_k<<<64, 256>>>(keys2, keys,  8192);

    gather_k<<<36, 256>>>();

    // NMS
    nms_mask_k<<<dim3(NWORDS, NWORDS), 64>>>();
    nms_reduce_k<<<1, 256>>>(out);
}

// round 8
// speedup vs baseline: 2.0194x; 1.2187x over previous
#include <cuda_runtime.h>
#include <cstdint>

// ---------------- problem constants ----------------
#define FMDIM   32
#define NPOS    1024            // 32*32
#define NANCH   9216            // 1024*9
#define NSORT   16384           // next pow2
#define NWORDS  144             // 9216/64
#define IOU_THR 0.7f
#define TOPK    300

// ---------------- scratch (static __device__, allocation-free) ----------------
__device__ float  g_col1[768 * 1024];          // im2col backbone        (3 MB)
__device__ float  g_feat[512 * 1024];          // backbone features      (2 MB)
__device__ float  g_col2[4608 * 1024];         // im2col rpn            (18 MB)
__device__ float  g_hid [512 * 1024];          // rpn hidden             (2 MB)
__device__ float  g_part[8 * 512 * 1024];      // split-K partials      (16 MB)
__device__ float  g_head[45 * 1024];           // rows 0..8 cls ch9..17, 9..44 box
__device__ float4 g_prop[NANCH];
__device__ unsigned long long g_keys [NSORT];
__device__ unsigned long long g_keys2[NSORT];
__device__ float4 g_boxes[NANCH];
__device__ unsigned long long g_mask[(size_t)NANCH * NWORDS]; // 10.6 MB

// ---------------- im2col for backbone (16x16 stride16 VALID) ----------------
__global__ void im2col1_k(const float* __restrict__ img)
{
    int idx = blockIdx.x * blockDim.x + threadIdx.x;   // 768*1024 threads
    int k = idx >> 10, p = idx & 1023;
    int ci = k >> 8, r = k & 255, ky = r >> 4, kx = r & 15;
    int py = p >> 5, px = p & 31;
    g_col1[idx] = img[ci * 512 * 512 + (py * 16 + ky) * 512 + (px * 16 + kx)];
}

// ---------------- im2col for rpn 3x3 SAME ----------------
__global__ void im2col2_k()
{
    int idx = blockIdx.x * blockDim.x + threadIdx.x;   // 4608*1024 threads
    int k = idx >> 10, p = idx & 1023;
    int ci = k / 9, r = k - ci * 9, dy = r / 3, dx = r - dy * 3;
    int py = p >> 5, px = p & 31;
    int y = py + dy - 1, x = px + dx - 1;
    float v = 0.0f;
    if ((unsigned)y < 32u && (unsigned)x < 32u) v = g_feat[ci * 1024 + y * 32 + x];
    g_col2[idx] = v;
}

// ---------------- split-K FP32 GEMM: P[s] = A[0:512][K] x B[K][1024] ----------------
// 128x128 tile, BK=8, 256 threads, 8x8 micro (4+4 split). M=512, N=1024 exact.
__global__ void gemm128_k(const float* __restrict__ A, const float* __restrict__ B,
                          float* __restrict__ P, int Ktot, int ksplit)
{
    __shared__ float As[8][132];   // [k][m]
    __shared__ float Bs[8][128];   // [k][n]

    const int bn = blockIdx.x * 128;
    const int bm = blockIdx.y * 128;
    const int s  = blockIdx.z;
    const int kbase = s * ksplit;
    const int tid = threadIdx.x;
    const int tx = tid & 15, ty = tid >> 4;
    const int alm = tid >> 1, alk = (tid & 1) * 4;     // A loader
    const int blk = tid >> 5, bln = (tid & 31) * 4;    // B loader

    const float* Aptr = A + (size_t)(bm + alm) * Ktot + kbase + alk;
    const float* Bptr = B + (size_t)(kbase + blk) * 1024 + bn + bln;

    float acc[8][8] = {};

    float4 av = *(const float4*)Aptr;
    float4 bv = *(const float4*)Bptr;

    for (int k0 = 0; k0 < ksplit; k0 += 8) {
        As[alk + 0][alm] = av.x; As[alk + 1][alm] = av.y;
        As[alk + 2][alm] = av.z; As[alk + 3][alm] = av.w;
        *(float4*)&Bs[blk][bln] = bv;
        __syncthreads();

        if (k0 + 8 < ksplit) {                         // prefetch next tile
            av = *(const float4*)(Aptr + k0 + 8);
            bv = *(const float4*)(Bptr + (size_t)(k0 + 8) * 1024);
        }

#pragma unroll
        for (int k = 0; k < 8; k++) {
            float4 a0 = *(const float4*)&As[k][ty * 4];
            float4 a1 = *(const float4*)&As[k][ty * 4 + 64];
            float4 b0 = *(const float4*)&Bs[k][tx * 4];
            float4 b1 = *(const float4*)&Bs[k][tx * 4 + 64];
            float a[8] = {a0.x, a0.y, a0.z, a0.w, a1.x, a1.y, a1.z, a1.w};
            float b[8] = {b0.x, b0.y, b0.z, b0.w, b1.x, b1.y, b1.z, b1.w};
#pragma unroll
            for (int i = 0; i < 8; i++)
#pragma unroll
                for (int j = 0; j < 8; j++)
                    acc[i][j] += a[i] * b[j];
        }
        __syncthreads();
    }

    float* Pp = P + (size_t)s * 512 * 1024;
#pragma unroll
    for (int ih = 0; ih < 2; ih++)
#pragma unroll
        for (int r = 0; r < 4; r++) {
            int i = ih * 4 + r;
            int m = bm + ih * 64 + ty * 4 + r;
            float4 o0 = make_float4(acc[i][0], acc[i][1], acc[i][2], acc[i][3]);
            float4 o1 = make_float4(acc[i][4], acc[i][5], acc[i][6], acc[i][7]);
            *(float4*)(Pp + (size_t)m * 1024 + bn + tx * 4)      = o0;
            *(float4*)(Pp + (size_t)m * 1024 + bn + tx * 4 + 64) = o1;
        }
}

// ---------------- deterministic split-K reduce (+bias+relu) ----------------
__global__ void reduce_k(const float* __restrict__ P, float* __restrict__ C,
                         const float* __restrict__ bias, int S, int relu)
{
    int idx = blockIdx.x * blockDim.x + threadIdx.x;   // 131072 threads (float4)
    int m = idx >> 8, n4 = (idx & 255) * 4;
    float4 acc = make_float4(0.f, 0.f, 0.f, 0.f);
    for (int s = 0; s < S; s++) {                      // fixed order
        float4 v = *(const float4*)(P + ((size_t)s * 512 + m) * 1024 + n4);
        acc.x += v.x; acc.y += v.y; acc.z += v.z; acc.w += v.w;
    }
    float bb = bias[m];
    acc.x += bb; acc.y += bb; acc.z += bb; acc.w += bb;
    if (relu) {
        acc.x = fmaxf(acc.x, 0.f); acc.y = fmaxf(acc.y, 0.f);
        acc.z = fmaxf(acc.z, 0.f); acc.w = fmaxf(acc.w, 0.f);
    }
    *(float4*)(C + (size_t)m * 1024 + n4) = acc;
}

// ---------------- small GEMM for heads (M<=64): C[M][1024]=A[M][K]xB ----------------
__global__ void gemm_k(const float* __restrict__ A, const float* __restrict__ B,
                       float* __restrict__ C, int M, int K,
                       const float* __restrict__ bias, int relu)
{
    __shared__ float As[16][68];
    __shared__ float Bs[16][64];

    const int bn  = blockIdx.x * 64;
    const int bm  = blockIdx.y * 64;
    const int tid = threadIdx.x;
    const int tx  = tid & 15, ty = tid >> 4;
    const int lm  = tid >> 2, lkq = (tid & 3) * 4;
    const int lkb = tid >> 4, ln4 = (tid & 15) * 4;

    float acc[4][4] = {};

    float4 av = make_float4(0.f, 0.f, 0.f, 0.f);
    if (bm + lm < M) av = *(const float4*)(A + (size_t)(bm + lm) * K + lkq);
    float4 bv = *(const float4*)(B + (size_t)lkb * 1024 + bn + ln4);

    for (int k0 = 0; k0 < K; k0 += 16) {
        As[lkq + 0][lm] = av.x; As[lkq + 1][lm] = av.y;
        As[lkq + 2][lm] = av.z; As[lkq + 3][lm] = av.w;
        *(float4*)&Bs[lkb][ln4] = bv;
        __syncthreads();

        int kn = k0 + 16;
        if (kn < K) {
            av = make_float4(0.f, 0.f, 0.f, 0.f);
            if (bm + lm < M) av = *(const float4*)(A + (size_t)(bm + lm) * K + kn + lkq);
            bv = *(const float4*)(B + (size_t)(kn + lkb) * 1024 + bn + ln4);
        }

#pragma unroll
        for (int k = 0; k < 16; k++) {
            float4 a = *(const float4*)&As[k][ty * 4];
            float4 b = *(const float4*)&Bs[k][tx * 4];
            acc[0][0] += a.x * b.x; acc[0][1] += a.x * b.y; acc[0][2] += a.x * b.z; acc[0][3] += a.x * b.w;
            acc[1][0] += a.y * b.x; acc[1][1] += a.y * b.y; acc[1][2] += a.y * b.z; acc[1][3] += a.y * b.w;
            acc[2][0] += a.z * b.x; acc[2][1] += a.z * b.y; acc[2][2] += a.z * b.z; acc[2][3] += a.z * b.w;
            acc[3][0] += a.w * b.x; acc[3][1] += a.w * b.y; acc[3][2] += a.w * b.z; acc[3][3] += a.w * b.w;
        }
        __syncthreads();
    }

#pragma unroll
    for (int r = 0; r < 4; r++) {
        int m = bm + ty * 4 + r;
        if (m < M) {
            float bb = bias[m];
            float4 o = make_float4(acc[r][0] + bb, acc[r][1] + bb, acc[r][2] + bb, acc[r][3] + bb);
            if (relu) {
                o.x = fmaxf(o.x, 0.f); o.y = fmaxf(o.y, 0.f);
                o.z = fmaxf(o.z, 0.f); o.w = fmaxf(o.w, 0.f);
            }
            *(float4*)(C + (size_t)m * 1024 + bn + tx * 4) = o;
        }
    }
}

// ---------------- decode proposals + build sort keys (unique keys) ----------------
__global__ void decode_k(const float* __restrict__ anchors)
{
    int i = blockIdx.x * blockDim.x + threadIdx.x;     // 16384 threads
    if (i >= NANCH) {
        if (i < NSORT) g_keys[i] = (0xFFFFFFFFull << 32) | (unsigned)i;  // unique pad
        return;
    }

    int p = i / 9, k = i - p * 9;
    float s  = g_head[k * 1024 + p];
    float d0 = g_head[(9 + k * 4 + 0) * 1024 + p];
    float d1 = g_head[(9 + k * 4 + 1) * 1024 + p];
    float d2 = g_head[(9 + k * 4 + 2) * 1024 + p];
    float d3 = g_head[(9 + k * 4 + 3) * 1024 + p];

    const float* a = anchors + (size_t)i * 4;
    float ax1 = a[0], ay1 = a[1], ax2 = a[2], ay2 = a[3];
    float wa = ax2 - ax1, ha = ay2 - ay1;
    float cxa = ax1 + 0.5f * wa, cya = ay1 + 0.5f * ha;
    float dw = fminf(fmaxf(d2, -4.f), 4.f);
    float dh = fminf(fmaxf(d3, -4.f), 4.f);
    float cx = cxa + d0 * wa, cy = cya + d1 * ha;
    float w  = wa * expf(dw), h = ha * expf(dh);
    float x1 = fmaxf(cx - 0.5f * w, 0.f);
    float y1 = fmaxf(cy - 0.5f * h, 0.f);
    float x2 = fminf(cx + 0.5f * w, 511.f);
    float y2 = fminf(cy + 0.5f * h, 511.f);
    g_prop[i] = make_float4(x1, y1, x2, y2);

    unsigned b   = __float_as_uint(s);
    unsigned asc = (b & 0x80000000u) ? ~b : (b | 0x80000000u);
    unsigned dsc = ~asc;
    g_keys[i] = ((unsigned long long)dsc << 32) | (unsigned)i;
}

// ---------------- stage A: 16 blocks each bitonic-sort 1024 keys ----------------
__global__ void sort1_k()
{
    __shared__ unsigned long long sk[1024];
    int base = blockIdx.x << 10, t = threadIdx.x;      // 512 threads
    sk[t]       = g_keys[base + t];
    sk[t + 512] = g_keys[base + t + 512];
    __syncthreads();
    for (int k = 2; k <= 1024; k <<= 1) {
        for (int j = k >> 1; j > 0; j >>= 1) {
            for (int e = t; e < 1024; e += 512) {
                int ixj = e ^ j;
                if (ixj > e) {
                    unsigned long long x = sk[e], y = sk[ixj];
                    bool up = ((e & k) == 0);
                    if (up ? (x > y) : (x < y)) { sk[e] = y; sk[ixj] = x; }
                }
            }
            __syncthreads();
        }
    }
    g_keys[base + t]       = sk[t];
    g_keys[base + t + 512] = sk[t + 512];
}

// ---------------- stage B: rank-merge pairs of sorted runs of length L ----------------
__global__ void merge_k(const unsigned long long* __restrict__ src,
                        unsigned long long* __restrict__ dst, int L)
{
    int i = blockIdx.x * blockDim.x + threadIdx.x;     // 16384 threads
    int pair = i / (2 * L);
    int base = pair * 2 * L;
    int r = i - base;
    unsigned long long v;
    const unsigned long long* other;
    int myidx;
    if (r < L) { v = src[base + r];     other = src + base + L; myidx = r; }
    else       { v = src[base + r];     other = src + base;     myidx = r - L; }
    int lo = 0, hi = L;                                // count other < v (keys unique)
    while (lo < hi) {
        int mid = (lo + hi) >> 1;
        if (other[mid] < v) lo = mid + 1; else hi = mid;
    }
    dst[base + myidx + lo] = v;
}

// ---------------- gather sorted boxes ----------------
__global__ void gather_k()
{
    int i = blockIdx.x * blockDim.x + threadIdx.x;
    if (i < NANCH) {
        int idx = (int)(g_keys[i] & 0xFFFFFFFFull);
        g_boxes[i] = g_prop[idx];
    }
}

// ---------------- NMS bitmask ----------------
__global__ void nms_mask_k()
{
    __shared__ float4 cb[64];
    int bxb = blockIdx.x, byb = blockIdx.y;
    int t = threadIdx.x;
    cb[t] = g_boxes[bxb * 64 + t];
    __syncthreads();

    int i = byb * 64 + t;
    unsigned long long m = 0ull;
    if (bxb >= byb) {
        float4 b  = g_boxes[i];
        float  ai = (b.z - b.x) * (b.w - b.y);
#pragma unroll 4
        for (int jj = 0; jj < 64; jj++) {
            int j = bxb * 64 + jj;
            if (j > i) {
                float4 c  = cb[jj];
                float  aj = (c.z - c.x) * (c.w - c.y);
                float iw = fmaxf(fminf(b.z, c.z) - fmaxf(b.x, c.x), 0.f);
                float ih = fmaxf(fminf(b.w, c.w) - fmaxf(b.y, c.y), 0.f);
                float inter = iw * ih;
                float iou = inter / (ai + aj - inter + 1e-9f);
                if (iou > IOU_THR) m |= (1ull << jj);
            }
        }
    }
    g_mask[(size_t)i * NWORDS + bxb] = m;
}

// ---------------- chunked greedy NMS reduce (exact serial semantics) ----------------
// Processes 64 candidates per chunk:
//   1. diagonal 64x64 block preloaded (double-buffered, prefetched during updates)
//   2. one thread resolves intra-chunk keep bits serially (smem/ALU only)
//   3. 144 word-owner threads batch-OR the mask rows of all accepted items
//      (independent loads -> MLP overlapped, one latency round per chunk)
//   4. early exit once 300 kept (prefix of kept list is unaffected by later i)
__global__ void nms_reduce_k(float* __restrict__ out)
{
    __shared__ unsigned long long remv[NWORDS];
    __shared__ unsigned long long keepw[NWORDS];
    __shared__ unsigned long long diag[2][64];
    __shared__ int chunkj[64];
    __shared__ int sel[TOPK];
    __shared__ int s_cnt, s_ccnt, s_done;

    int t = threadIdx.x;                               // 192 threads
    if (t < NWORDS) { remv[t] = 0ull; keepw[t] = 0ull; }
    if (t == 0) { s_cnt = 0; s_done = 0; }
    if (t < 64) diag[0][t] = g_mask[(size_t)t * NWORDS + 0];   // chunk 0 diagonal
    __syncthreads();

    for (int c = 0; c < NWORDS; c++) {
        int buf = c & 1;
        if (t == 0) {
            unsigned long long w  = remv[c];
            unsigned long long kw = 0ull;
            int cc = 0;
            int cnt = s_cnt;
            for (int j = 0; j < 64; j++) {
                if (!((w >> j) & 1ull)) {
                    sel[cnt++] = c * 64 + j;
                    kw |= 1ull << j;
                    chunkj[cc++] = j;
                    if (cnt >= TOPK) break;            // later decisions can't change prefix
                    w |= diag[buf][j];                 // intra-chunk suppression
                }
            }
            keepw[c] = kw;
            s_cnt = cnt;
            s_ccnt = cc;
            if (cnt >= TOPK) s_done = 1;
        }
        __syncthreads();
        if (s_done) break;

        // prefetch next chunk's diagonal block (warps 2-3)
        if (t >= 64 && t < 128 && c + 1 < NWORDS) {
            int tt = t - 64;
            diag[buf ^ 1][tt] =
                g_mask[(size_t)((c + 1) * 64 + tt) * NWORDS + (c + 1)];
        }

        // batched suppression: OR accepted rows into future remv words
        if (t < NWORDS && t > c) {
            unsigned long long r = remv[t];
            int cc = s_ccnt;
            for (int q = 0; q < cc; q++)               // independent loads (MLP)
                r |= g_mask[(size_t)(c * 64 + chunkj[q]) * NWORDS + t];
            remv[t] = r;
        }
        __syncthreads();
    }
    __syncthreads();

    // fewer than 300 kept: stable argsort(~keep) appends suppressed in index order
    if (t == 0 && s_cnt < TOPK) {
        int cnt = s_cnt;
        for (int i = 0; i < NANCH && cnt < TOPK; i++)
            if (!((keepw[i >> 6] >> (i & 63)) & 1ull)) sel[cnt++] = i;
        s_cnt = cnt;
    }
    __syncthreads();

    for (int s = t; s < TOPK; s += blockDim.x) {
        float4 b = g_boxes[sel[s]];
        out[s * 4 + 0] = b.x; out[s * 4 + 1] = b.y;
        out[s * 4 + 2] = b.z; out[s * 4 + 3] = b.w;
    }
}

// ---------------- launch ----------------
extern "C" void kernel_launch(void* const* d_in, const int* in_sizes, int n_in,
                              void* d_out, int out_size)
{
    const float* img     = (const float*)d_in[0];
    const float* anchors = (const float*)d_in[1];
    const float* w_bb    = (const float*)d_in[2];
    const float* b_bb    = (const float*)d_in[3];
    const float* w_rpn   = (const float*)d_in[4];
    const float* b_rpn   = (const float*)d_in[5];
    const float* w_cls   = (const float*)d_in[6];
    const float* b_cls   = (const float*)d_in[7];
    const float* w_box   = (const float*)d_in[8];
    const float* b_box   = (const float*)d_in[9];
    float* out = (float*)d_out;

    float *col1, *feat, *col2, *hid, *head, *part;
    unsigned long long *keys, *keys2;
    cudaGetSymbolAddress((void**)&col1,  g_col1);
    cudaGetSymbolAddress((void**)&feat,  g_feat);
    cudaGetSymbolAddress((void**)&col2,  g_col2);
    cudaGetSymbolAddress((void**)&hid,   g_hid);
    cudaGetSymbolAddress((void**)&head,  g_head);
    cudaGetSymbolAddress((void**)&part,  g_part);
    cudaGetSymbolAddress((void**)&keys,  g_keys);
    cudaGetSymbolAddress((void**)&keys2, g_keys2);

    // backbone conv: split-K 4 (K=768, ksplit=192)
    im2col1_k<<<3072, 256>>>(img);
    gemm128_k<<<dim3(8, 4, 4), 256>>>(w_bb, col1, part, 768, 192);
    reduce_k<<<512, 256>>>(part, feat, b_bb, 4, 1);

    // rpn conv: split-K 8 (K=4608, ksplit=576)
    im2col2_k<<<18432, 256>>>();
    gemm128_k<<<dim3(8, 4, 8), 256>>>(w_rpn, col2, part, 4608, 576);
    reduce_k<<<512, 256>>>(part, hid, b_rpn, 8, 1);

    // heads (1x1 convs)
    gemm_k<<<dim3(16, 1), 256>>>(w_cls + 9 * 512, hid, head,            9,  512, b_cls + 9, 0);
    gemm_k<<<dim3(16, 1), 256>>>(w_box,           hid, head + 9 * 1024, 36, 512, b_box,     0);

    // decode + keys
    decode_k<<<64, 256>>>(anchors);

    // sort: 16 local bitonic sorts, then 4 rank-merge rounds
    sort1_k<<<16, 512>>>();
    merge_k<<<64, 256>>>(keys,  keys2, 1024);
    merge_k<<<64, 256>>>(keys2, keys,  2048);
    merge_k<<<64, 256>>>(keys,  keys2, 4096);
    merge_k<<<64, 256>>>(keys2, keys,  8192);

    gather_k<<<36, 256>>>();

    // NMS
    nms_mask_k<<<dim3(NWORDS, NWORDS), 64>>>();
    nms_reduce_k<<<1, 192>>>(out);
}

// round 9
// speedup vs baseline: 2.0300x; 1.0052x over previous
#include <cuda_runtime.h>
#include <cstdint>

// ---------------- problem constants ----------------
#define FMDIM   32
#define NPOS    1024            // 32*32
#define NANCH   9216            // 1024*9
#define NSORT   16384           // next pow2
#define NWORDS  144             // 9216/64
#define IOU_THR 0.7f
#define TOPK    300

// ---------------- scratch (static __device__, allocation-free) ----------------
__device__ float  g_col1[768 * 1024];          // im2col backbone        (3 MB)
__device__ float  g_feat[512 * 1024];          // backbone features      (2 MB)
__device__ float  g_col2[4608 * 1024];         // im2col rpn            (18 MB)
__device__ float  g_hid [512 * 1024];          // rpn hidden             (2 MB)
__device__ float  g_part[8 * 512 * 1024];      // split-K partials      (16 MB)
__device__ float  g_head[45 * 1024];           // rows 0..8 cls ch9..17, 9..44 box
__device__ float4 g_prop[NANCH];
__device__ unsigned long long g_keys [NSORT];
__device__ unsigned long long g_keys2[NSORT];
__device__ float4 g_boxes[NANCH];
__device__ unsigned long long g_mask[(size_t)NANCH * NWORDS]; // 10.6 MB

// ---------------- packed f32x2 helpers (Blackwell; ptxas never auto-fuses) ----------------
__device__ __forceinline__ void ffma2(unsigned long long& d,
                                      unsigned long long a, unsigned long long b)
{
    asm("fma.rn.f32x2 %0, %1, %2, %0;" : "+l"(d) : "l"(a), "l"(b));
}
__device__ __forceinline__ unsigned long long pack2(float lo, float hi)
{
    unsigned long long r;
    asm("mov.b64 %0, {%1, %2};" : "=l"(r) : "f"(lo), "f"(hi));
    return r;
}
__device__ __forceinline__ float2 unpack2(unsigned long long v)
{
    float2 r;
    asm("mov.b64 {%0, %1}, %2;" : "=f"(r.x), "=f"(r.y) : "l"(v));
    return r;
}

// ---------------- im2col for backbone (16x16 stride16 VALID) ----------------
__global__ void im2col1_k(const float* __restrict__ img)
{
    int idx = blockIdx.x * blockDim.x + threadIdx.x;   // 768*1024 threads
    int k = idx >> 10, p = idx & 1023;
    int ci = k >> 8, r = k & 255, ky = r >> 4, kx = r & 15;
    int py = p >> 5, px = p & 31;
    g_col1[idx] = img[ci * 512 * 512 + (py * 16 + ky) * 512 + (px * 16 + kx)];
}

// ---------------- im2col for rpn 3x3 SAME ----------------
__global__ void im2col2_k()
{
    int idx = blockIdx.x * blockDim.x + threadIdx.x;   // 4608*1024 threads
    int k = idx >> 10, p = idx & 1023;
    int ci = k / 9, r = k - ci * 9, dy = r / 3, dx = r - dy * 3;
    int py = p >> 5, px = p & 31;
    int y = py + dy - 1, x = px + dx - 1;
    float v = 0.0f;
    if ((unsigned)y < 32u && (unsigned)x < 32u) v = g_feat[ci * 1024 + y * 32 + x];
    g_col2[idx] = v;
}

// ---------------- split-K FP32 GEMM (fma.rn.f32x2): P[s] = A x B ----------------
// 128x128 tile, BK=8, 256 threads, 8x8 micro held as 8x4 packed f32x2 accumulators.
// Per-element arithmetic is IEEE fp32 FMA in the same order as the scalar version
// -> bit-identical results, 2x FFMA pipe throughput.
__global__ void gemm128_k(const float* __restrict__ A, const float* __restrict__ B,
                          float* __restrict__ P, int Ktot, int ksplit)
{
    __shared__ float As[8][132];   // [k][m]
    __shared__ float Bs[8][128];   // [k][n]

    const int bn = blockIdx.x * 128;
    const int bm = blockIdx.y * 128;
    const int s  = blockIdx.z;
    const int kbase = s * ksplit;
    const int tid = threadIdx.x;
    const int tx = tid & 15, ty = tid >> 4;
    const int alm = tid >> 1, alk = (tid & 1) * 4;     // A loader
    const int blk = tid >> 5, bln = (tid & 31) * 4;    // B loader

    const float* Aptr = A + (size_t)(bm + alm) * Ktot + kbase + alk;
    const float* Bptr = B + (size_t)(kbase + blk) * 1024 + bn + bln;

    unsigned long long acc[8][4];
#pragma unroll
    for (int i = 0; i < 8; i++)
#pragma unroll
        for (int j = 0; j < 4; j++) acc[i][j] = 0ull;  // (0.f,0.f)

    float4 av = *(const float4*)Aptr;
    float4 bv = *(const float4*)Bptr;

    for (int k0 = 0; k0 < ksplit; k0 += 8) {
        As[alk + 0][alm] = av.x; As[alk + 1][alm] = av.y;
        As[alk + 2][alm] = av.z; As[alk + 3][alm] = av.w;
        *(float4*)&Bs[blk][bln] = bv;
        __syncthreads();

        if (k0 + 8 < ksplit) {                         // prefetch next tile
            av = *(const float4*)(Aptr + k0 + 8);
            bv = *(const float4*)(Bptr + (size_t)(k0 + 8) * 1024);
        }

#pragma unroll
        for (int k = 0; k < 8; k++) {
            float4 a0 = *(const float4*)&As[k][ty * 4];
            float4 a1 = *(const float4*)&As[k][ty * 4 + 64];
            float4 b0 = *(const float4*)&Bs[k][tx * 4];
            float4 b1 = *(const float4*)&Bs[k][tx * 4 + 64];
            unsigned long long bb[4] = {
                pack2(b0.x, b0.y), pack2(b0.z, b0.w),
                pack2(b1.x, b1.y), pack2(b1.z, b1.w)
            };
            float a[8] = {a0.x, a0.y, a0.z, a0.w, a1.x, a1.y, a1.z, a1.w};
#pragma unroll
            for (int i = 0; i < 8; i++) {
                unsigned long long ad = pack2(a[i], a[i]);
#pragma unroll
                for (int j = 0; j < 4; j++)
                    ffma2(acc[i][j], ad, bb[j]);
            }
        }
        __syncthreads();
    }

    float* Pp = P + (size_t)s * 512 * 1024;
#pragma unroll
    for (int ih = 0; ih < 2; ih++)
#pragma unroll
        for (int r = 0; r < 4; r++) {
            int i = ih * 4 + r;
            int m = bm + ih * 64 + ty * 4 + r;
            float2 p0 = unpack2(acc[i][0]), p1 = unpack2(acc[i][1]);
            float2 p2 = unpack2(acc[i][2]), p3 = unpack2(acc[i][3]);
            float4 o0 = make_float4(p0.x, p0.y, p1.x, p1.y);
            float4 o1 = make_float4(p2.x, p2.y, p3.x, p3.y);
            *(float4*)(Pp + (size_t)m * 1024 + bn + tx * 4)      = o0;
            *(float4*)(Pp + (size_t)m * 1024 + bn + tx * 4 + 64) = o1;
        }
}

// ---------------- deterministic split-K reduce (+bias+relu) ----------------
__global__ void reduce_k(const float* __restrict__ P, float* __restrict__ C,
                         const float* __restrict__ bias, int S, int relu)
{
    int idx = blockIdx.x * blockDim.x + threadIdx.x;   // 131072 threads (float4)
    int m = idx >> 8, n4 = (idx & 255) * 4;
    float4 acc = make_float4(0.f, 0.f, 0.f, 0.f);
    for (int s = 0; s < S; s++) {                      // fixed order
        float4 v = *(const float4*)(P + ((size_t)s * 512 + m) * 1024 + n4);
        acc.x += v.x; acc.y += v.y; acc.z += v.z; acc.w += v.w;
    }
    float bb = bias[m];
    acc.x += bb; acc.y += bb; acc.z += bb; acc.w += bb;
    if (relu) {
        acc.x = fmaxf(acc.x, 0.f); acc.y = fmaxf(acc.y, 0.f);
        acc.z = fmaxf(acc.z, 0.f); acc.w = fmaxf(acc.w, 0.f);
    }
    *(float4*)(C + (size_t)m * 1024 + n4) = acc;
}

// ---------------- small GEMM for heads (M<=64): C[M][1024]=A[M][K]xB ----------------
__global__ void gemm_k(const float* __restrict__ A, const float* __restrict__ B,
                       float* __restrict__ C, int M, int K,
                       const float* __restrict__ bias, int relu)
{
    __shared__ float As[16][68];
    __shared__ float Bs[16][64];

    const int bn  = blockIdx.x * 64;
    const int bm  = blockIdx.y * 64;
    const int tid = threadIdx.x;
    const int tx  = tid & 15, ty = tid >> 4;
    const int lm  = tid >> 2, lkq = (tid & 3) * 4;
    const int lkb = tid >> 4, ln4 = (tid & 15) * 4;

    float acc[4][4] = {};

    float4 av = make_float4(0.f, 0.f, 0.f, 0.f);
    if (bm + lm < M) av = *(const float4*)(A + (size_t)(bm + lm) * K + lkq);
    float4 bv = *(const float4*)(B + (size_t)lkb * 1024 + bn + ln4);

    for (int k0 = 0; k0 < K; k0 += 16) {
        As[lkq + 0][lm] = av.x; As[lkq + 1][lm] = av.y;
        As[lkq + 2][lm] = av.z; As[lkq + 3][lm] = av.w;
        *(float4*)&Bs[lkb][ln4] = bv;
        __syncthreads();

        int kn = k0 + 16;
        if (kn < K) {
            av = make_float4(0.f, 0.f, 0.f, 0.f);
            if (bm + lm < M) av = *(const float4*)(A + (size_t)(bm + lm) * K + kn + lkq);
            bv = *(const float4*)(B + (size_t)(kn + lkb) * 1024 + bn + ln4);
        }

#pragma unroll
        for (int k = 0; k < 16; k++) {
            float4 a = *(const float4*)&As[k][ty * 4];
            float4 b = *(const float4*)&Bs[k][tx * 4];
            acc[0][0] += a.x * b.x; acc[0][1] += a.x * b.y; acc[0][2] += a.x * b.z; acc[0][3] += a.x * b.w;
            acc[1][0] += a.y * b.x; acc[1][1] += a.y * b.y; acc[1][2] += a.y * b.z; acc[1][3] += a.y * b.w;
            acc[2][0] += a.z * b.x; acc[2][1] += a.z * b.y; acc[2][2] += a.z * b.z; acc[2][3] += a.z * b.w;
            acc[3][0] += a.w * b.x; acc[3][1] += a.w * b.y; acc[3][2] += a.w * b.z; acc[3][3] += a.w * b.w;
        }
        __syncthreads();
    }

#pragma unroll
    for (int r = 0; r < 4; r++) {
        int m = bm + ty * 4 + r;
        if (m < M) {
            float bb = bias[m];
            float4 o = make_float4(acc[r][0] + bb, acc[r][1] + bb, acc[r][2] + bb, acc[r][3] + bb);
            if (relu) {
                o.x = fmaxf(o.x, 0.f); o.y = fmaxf(o.y, 0.f);
                o.z = fmaxf(o.z, 0.f); o.w = fmaxf(o.w, 0.f);
            }
            *(float4*)(C + (size_t)m * 1024 + bn + tx * 4) = o;
        }
    }
}

// ---------------- decode proposals + build sort keys (unique keys) ----------------
__global__ void decode_k(const float* __restrict__ anchors)
{
    int i = blockIdx.x * blockDim.x + threadIdx.x;     // 16384 threads
    if (i >= NANCH) {
        if (i < NSORT) g_keys[i] = (0xFFFFFFFFull << 32) | (unsigned)i;  // unique pad
        return;
    }

    int p = i / 9, k = i - p * 9;
    float s  = g_head[k * 1024 + p];
    float d0 = g_head[(9 + k * 4 + 0) * 1024 + p];
    float d1 = g_head[(9 + k * 4 + 1) * 1024 + p];
    float d2 = g_head[(9 + k * 4 + 2) * 1024 + p];
    float d3 = g_head[(9 + k * 4 + 3) * 1024 + p];

    const float* a = anchors + (size_t)i * 4;
    float ax1 = a[0], ay1 = a[1], ax2 = a[2], ay2 = a[3];
    float wa = ax2 - ax1, ha = ay2 - ay1;
    float cxa = ax1 + 0.5f * wa, cya = ay1 + 0.5f * ha;
    float dw = fminf(fmaxf(d2, -4.f), 4.f);
    float dh = fminf(fmaxf(d3, -4.f), 4.f);
    float cx = cxa + d0 * wa, cy = cya + d1 * ha;
    float w  = wa * expf(dw), h = ha * expf(dh);
    float x1 = fmaxf(cx - 0.5f * w, 0.f);
    float y1 = fmaxf(cy - 0.5f * h, 0.f);
    float x2 = fminf(cx + 0.5f * w, 511.f);
    float y2 = fminf(cy + 0.5f * h, 511.f);
    g_prop[i] = make_float4(x1, y1, x2, y2);

    unsigned b   = __float_as_uint(s);
    unsigned asc = (b & 0x80000000u) ? ~b : (b | 0x80000000u);
    unsigned dsc = ~asc;
    g_keys[i] = ((unsigned long long)dsc << 32) | (unsigned)i;
}

// ---------------- stage A: 16 blocks each bitonic-sort 1024 keys ----------------
__global__ void sort1_k()
{
    __shared__ unsigned long long sk[1024];
    int base = blockIdx.x << 10, t = threadIdx.x;      // 512 threads
    sk[t]       = g_keys[base + t];
    sk[t + 512] = g_keys[base + t + 512];
    __syncthreads();
    for (int k = 2; k <= 1024; k <<= 1) {
        for (int j = k >> 1; j > 0; j >>= 1) {
            for (int e = t; e < 1024; e += 512) {
                int ixj = e ^ j;
                if (ixj > e) {
                    unsigned long long x = sk[e], y = sk[ixj];
                    bool up = ((e & k) == 0);
                    if (up ? (x > y) : (x < y)) { sk[e] = y; sk[ixj] = x; }
                }
            }
            __syncthreads();
        }
    }
    g_keys[base + t]       = sk[t];
    g_keys[base + t + 512] = sk[t + 512];
}

// ---------------- stage B: rank-merge pairs of sorted runs of length L ----------------
__global__ void merge_k(const unsigned long long* __restrict__ src,
                        unsigned long long* __restrict__ dst, int L)
{
    int i = blockIdx.x * blockDim.x + threadIdx.x;     // 16384 threads
    int pair = i / (2 * L);
    int base = pair * 2 * L;
    int r = i - base;
    unsigned long long v;
    const unsigned long long* other;
    int myidx;
    if (r < L) { v = src[base + r];     other = src + base + L; myidx = r; }
    else       { v = src[base + r];     other = src + base;     myidx = r - L; }
    int lo = 0, hi = L;                                // count other < v (keys unique)
    while (lo < hi) {
        int mid = (lo + hi) >> 1;
        if (other[mid] < v) lo = mid + 1; else hi = mid;
    }
    dst[base + myidx + lo] = v;
}

// ---------------- gather sorted boxes ----------------
__global__ void gather_k()
{
    int i = blockIdx.x * blockDim.x + threadIdx.x;
    if (i < NANCH) {
        int idx = (int)(g_keys[i] & 0xFFFFFFFFull);
        g_boxes[i] = g_prop[idx];
    }
}

// ---------------- NMS bitmask ----------------
__global__ void nms_mask_k()
{
    __shared__ float4 cb[64];
    int bxb = blockIdx.x, byb = blockIdx.y;
    int t = threadIdx.x;
    cb[t] = g_boxes[bxb * 64 + t];
    __syncthreads();

    int i = byb * 64 + t;
    unsigned long long m = 0ull;
    if (bxb >= byb) {
        float4 b  = g_boxes[i];
        float  ai = (b.z - b.x) * (b.w - b.y);
#pragma unroll 4
        for (int jj = 0; jj < 64; jj++) {
            int j = bxb * 64 + jj;
            if (j > i) {
                float4 c  = cb[jj];
                float  aj = (c.z - c.x) * (c.w - c.y);
                float iw = fmaxf(fminf(b.z, c.z) - fmaxf(b.x, c.x), 0.f);
                float ih = fmaxf(fminf(b.w, c.w) - fmaxf(b.y, c.y), 0.f);
                float inter = iw * ih;
                float iou = inter / (ai + aj - inter + 1e-9f);
                if (iou > IOU_THR) m |= (1ull << jj);
            }
        }
    }
    g_mask[(size_t)i * NWORDS + bxb] = m;
}

// ---------------- chunked greedy NMS reduce (exact serial semantics) ----------------
__global__ void nms_reduce_k(float* __restrict__ out)
{
    __shared__ unsigned long long remv[NWORDS];
    __shared__ unsigned long long keepw[NWORDS];
    __shared__ unsigned long long diag[2][64];
    __shared__ int chunkj[64];
    __shared__ int sel[TOPK];
    __shared__ int s_cnt, s_ccnt, s_done;

    int t = threadIdx.x;                               // 192 threads
    if (t < NWORDS) { remv[t] = 0ull; keepw[t] = 0ull; }
    if (t == 0) { s_cnt = 0; s_done = 0; }
    if (t < 64) diag[0][t] = g_mask[(size_t)t * NWORDS + 0];   // chunk 0 diagonal
    __syncthreads();

    for (int c = 0; c < NWORDS; c++) {
        int buf = c & 1;
        if (t == 0) {
            unsigned long long w  = remv[c];
            unsigned long long kw = 0ull;
            int cc = 0;
            int cnt = s_cnt;
            for (int j = 0; j < 64; j++) {
                if (!((w >> j) & 1ull)) {
                    sel[cnt++] = c * 64 + j;
                    kw |= 1ull << j;
                    chunkj[cc++] = j;
                    if (cnt >= TOPK) break;            // later decisions can't change prefix
                    w |= diag[buf][j];                 // intra-chunk suppression
                }
            }
            keepw[c] = kw;
            s_cnt = cnt;
            s_ccnt = cc;
            if (cnt >= TOPK) s_done = 1;
        }
        __syncthreads();
        if (s_done) break;

        // prefetch next chunk's diagonal block (warps 2-3)
        if (t >= 64 && t < 128 && c + 1 < NWORDS) {
            int tt = t - 64;
            diag[buf ^ 1][tt] =
                g_mask[(size_t)((c + 1) * 64 + tt) * NWORDS + (c + 1)];
        }

        // batched suppression: OR accepted rows into future remv words
        if (t < NWORDS && t > c) {
            unsigned long long r = remv[t];
            int cc = s_ccnt;
            for (int q = 0; q < cc; q++)               // independent loads (MLP)
                r |= g_mask[(size_t)(c * 64 + chunkj[q]) * NWORDS + t];
            remv[t] = r;
        }
        __syncthreads();
    }
    __syncthreads();

    // fewer than 300 kept: stable argsort(~keep) appends suppressed in index order
    if (t == 0 && s_cnt < TOPK) {
        int cnt = s_cnt;
        for (int i = 0; i < NANCH && cnt < TOPK; i++)
            if (!((keepw[i >> 6] >> (i & 63)) & 1ull)) sel[cnt++] = i;
        s_cnt = cnt;
    }
    __syncthreads();

    for (int s = t; s < TOPK; s += blockDim.x) {
        float4 b = g_boxes[sel[s]];
        out[s * 4 + 0] = b.x; out[s * 4 + 1] = b.y;
        out[s * 4 + 2] = b.z; out[s * 4 + 3] = b.w;
    }
}

// ---------------- launch ----------------
extern "C" void kernel_launch(void* const* d_in, const int* in_sizes, int n_in,
                              void* d_out, int out_size)
{
    const float* img     = (const float*)d_in[0];
    const float* anchors = (const float*)d_in[1];
    const float* w_bb    = (const float*)d_in[2];
    const float* b_bb    = (const float*)d_in[3];
    const float* w_rpn   = (const float*)d_in[4];
    const float* b_rpn   = (const float*)d_in[5];
    const float* w_cls   = (const float*)d_in[6];
    const float* b_cls   = (const float*)d_in[7];
    const float* w_box   = (const float*)d_in[8];
    const float* b_box   = (const float*)d_in[9];
    float* out = (float*)d_out;

    float *col1, *feat, *col2, *hid, *head, *part;
    unsigned long long *keys, *keys2;
    cudaGetSymbolAddress((void**)&col1,  g_col1);
    cudaGetSymbolAddress((void**)&feat,  g_feat);
    cudaGetSymbolAddress((void**)&col2,  g_col2);
    cudaGetSymbolAddress((void**)&hid,   g_hid);
    cudaGetSymbolAddress((void**)&head,  g_head);
    cudaGetSymbolAddress((void**)&part,  g_part);
    cudaGetSymbolAddress((void**)&keys,  g_keys);
    cudaGetSymbolAddress((void**)&keys2, g_keys2);

    // backbone conv: split-K 4 (K=768, ksplit=192)
    im2col1_k<<<3072, 256>>>(img);
    gemm128_k<<<dim3(8, 4, 4), 256>>>(w_bb, col1, part, 768, 192);
    reduce_k<<<512, 256>>>(part, feat, b_bb, 4, 1);

    // rpn conv: split-K 8 (K=4608, ksplit=576)
    im2col2_k<<<18432, 256>>>();
    gemm128_k<<<dim3(8, 4, 8), 256>>>(w_rpn, col2, part, 4608, 576);
    reduce_k<<<512, 256>>>(part, hid, b_rpn, 8, 1);

    // heads (1x1 convs)
    gemm_k<<<dim3(16, 1), 256>>>(w_cls + 9 * 512, hid, head,            9,  512, b_cls + 9, 0);
    gemm_k<<<dim3(16, 1), 256>>>(w_box,           hid, head + 9 * 1024, 36, 512, b_box,     0);

    // decode + keys
    decode_k<<<64, 256>>>(anchors);

    // sort: 16 local bitonic sorts, then 4 rank-merge rounds
    sort1_k<<<16, 512>>>();
    merge_k<<<64, 256>>>(keys,  keys2, 1024);
    merge_k<<<64, 256>>>(keys2, keys,  2048);
    merge_k<<<64, 256>>>(keys,  keys2, 4096);
    merge_k<<<64, 256>>>(keys2, keys,  8192);

    gather_k<<<36, 256>>>();

    // NMS
    nms_mask_k<<<dim3(NWORDS, NWORDS), 64>>>();
    nms_reduce_k<<<1, 192>>>(out);
}

// round 10
// speedup vs baseline: 2.1075x; 1.0382x over previous
#include <cuda_runtime.h>
#include <cstdint>

// ---------------- problem constants ----------------
#define FMDIM   32
#define NPOS    1024            // 32*32
#define NANCH   9216            // 1024*9
#define NSORT   16384           // next pow2
#define NWORDS  144             // 9216/64
#define IOU_THR 0.7f
#define TOPK    300

// ---------------- scratch (static __device__, allocation-free) ----------------
__device__ float  g_col1[768 * 1024];          // im2col backbone        (3 MB)
__device__ float  g_feat[512 * 1024];          // backbone features      (2 MB)
__device__ float  g_hid [512 * 1024];          // rpn hidden             (2 MB)
__device__ float  g_part[8 * 512 * 1024];      // split-K partials      (16 MB)
__device__ float  g_head[45 * 1024];           // rows 0..8 cls ch9..17, 9..44 box
__device__ float  g_wh[45 * 512];              // staged head weights
__device__ float  g_bh[45];                    // staged head bias
__device__ float4 g_prop[NANCH];
__device__ unsigned long long g_keys [NSORT];
__device__ unsigned long long g_keys2[NSORT];
__device__ float4 g_boxes[NANCH];
__device__ unsigned long long g_mask[(size_t)NANCH * NWORDS]; // 10.6 MB

// ---------------- packed f32x2 helpers ----------------
__device__ __forceinline__ void ffma2(unsigned long long& d,
                                      unsigned long long a, unsigned long long b)
{
    asm("fma.rn.f32x2 %0, %1, %2, %0;" : "+l"(d) : "l"(a), "l"(b));
}
__device__ __forceinline__ unsigned long long pack2(float lo, float hi)
{
    unsigned long long r;
    asm("mov.b64 %0, {%1, %2};" : "=l"(r) : "f"(lo), "f"(hi));
    return r;
}
__device__ __forceinline__ float2 unpack2(unsigned long long v)
{
    float2 r;
    asm("mov.b64 {%0, %1}, %2;" : "=f"(r.x), "=f"(r.y) : "l"(v));
    return r;
}

// ---------------- im2col for backbone (16x16 stride16 VALID) ----------------
__global__ void im2col1_k(const float* __restrict__ img)
{
    int idx = blockIdx.x * blockDim.x + threadIdx.x;   // 768*1024 threads
    int k = idx >> 10, p = idx & 1023;
    int ci = k >> 8, r = k & 255, ky = r >> 4, kx = r & 15;
    int py = p >> 5, px = p & 31;
    g_col1[idx] = img[ci * 512 * 512 + (py * 16 + ky) * 512 + (px * 16 + kx)];
}

// ---------------- generic split-K GEMM (B from memory), FFMA2 micro ----------------
__global__ void __launch_bounds__(256, 2)
gemm128_k(const float* __restrict__ A, const float* __restrict__ B,
          float* __restrict__ P, int Ktot, int ksplit)
{
    __shared__ float As[8][132];   // [k][m]
    __shared__ float Bs[8][128];   // [k][n]

    const int bn = blockIdx.x * 128;
    const int bm = blockIdx.y * 128;
    const int s  = blockIdx.z;
    const int kbase = s * ksplit;
    const int tid = threadIdx.x;
    const int tx = tid & 15, ty = tid >> 4;
    const int alm = tid >> 1, alk = (tid & 1) * 4;     // A loader
    const int blk = tid >> 5, bln = (tid & 31) * 4;    // B loader

    const float* Aptr = A + (size_t)(bm + alm) * Ktot + kbase + alk;
    const float* Bptr = B + (size_t)(kbase + blk) * 1024 + bn + bln;

    unsigned long long acc[8][4];
#pragma unroll
    for (int i = 0; i < 8; i++)
#pragma unroll
        for (int j = 0; j < 4; j++) acc[i][j] = 0ull;

    float4 av = *(const float4*)Aptr;
    float4 bv = *(const float4*)Bptr;

    for (int k0 = 0; k0 < ksplit; k0 += 8) {
        As[alk + 0][alm] = av.x; As[alk + 1][alm] = av.y;
        As[alk + 2][alm] = av.z; As[alk + 3][alm] = av.w;
        *(float4*)&Bs[blk][bln] = bv;
        __syncthreads();

        if (k0 + 8 < ksplit) {
            av = *(const float4*)(Aptr + k0 + 8);
            bv = *(const float4*)(Bptr + (size_t)(k0 + 8) * 1024);
        }

#pragma unroll
        for (int k = 0; k < 8; k++) {
            float4 a0 = *(const float4*)&As[k][ty * 4];
            float4 a1 = *(const float4*)&As[k][ty * 4 + 64];
            float4 b0 = *(const float4*)&Bs[k][tx * 4];
            float4 b1 = *(const float4*)&Bs[k][tx * 4 + 64];
            unsigned long long bb[4] = {
                pack2(b0.x, b0.y), pack2(b0.z, b0.w),
                pack2(b1.x, b1.y), pack2(b1.z, b1.w)
            };
            float a[8] = {a0.x, a0.y, a0.z, a0.w, a1.x, a1.y, a1.z, a1.w};
#pragma unroll
            for (int i = 0; i < 8; i++) {
                unsigned long long ad = pack2(a[i], a[i]);
#pragma unroll
                for (int j = 0; j < 4; j++)
                    ffma2(acc[i][j], ad, bb[j]);
            }
        }
        __syncthreads();
    }

    float* Pp = P + (size_t)s * 512 * 1024;
#pragma unroll
    for (int ih = 0; ih < 2; ih++)
#pragma unroll
        for (int r = 0; r < 4; r++) {
            int i = ih * 4 + r;
            int m = bm + ih * 64 + ty * 4 + r;
            float2 p0 = unpack2(acc[i][0]), p1 = unpack2(acc[i][1]);
            float2 p2 = unpack2(acc[i][2]), p3 = unpack2(acc[i][3]);
            *(float4*)(Pp + (size_t)m * 1024 + bn + tx * 4)      = make_float4(p0.x, p0.y, p1.x, p1.y);
            *(float4*)(Pp + (size_t)m * 1024 + bn + tx * 4 + 64) = make_float4(p2.x, p2.y, p3.x, p3.y);
        }
}

// ---------------- rpn GEMM with fused im2col (B built from g_feat on the fly) ----------------
// B[k][p] = feat[ci][py+dy-1][px+dx-1], k=ci*9+dy*3+dx, p=py*32+px, 0 if out of bounds.
__device__ __forceinline__ float4 load_feat_quad(int k, int p)
{
    int ci = k / 9, r = k - ci * 9, dy = r / 3, dx = r - dy * 3;
    int py = p >> 5, px = p & 31;                      // px multiple of 4
    int y = py + dy - 1;
    int x0 = px + dx - 1;
    float4 v = make_float4(0.f, 0.f, 0.f, 0.f);
    if ((unsigned)y < 32u) {
        const float* frow = g_feat + ci * 1024 + y * 32 + x0;
        v.x = (x0 >= 0) ? frow[0] : 0.f;               // only first elem can underflow
        v.y = frow[1];
        v.z = frow[2];
        v.w = (x0 + 3 <= 31) ? frow[3] : 0.f;          // only last elem can overflow
    }
    return v;
}

__global__ void __launch_bounds__(256, 2)
gemm128rpn_k(const float* __restrict__ A, float* __restrict__ P, int ksplit)
{
    __shared__ float As[8][132];
    __shared__ float Bs[8][128];

    const int bn = blockIdx.x * 128;
    const int bm = blockIdx.y * 128;
    const int s  = blockIdx.z;
    const int kbase = s * ksplit;
    const int tid = threadIdx.x;
    const int tx = tid & 15, ty = tid >> 4;
    const int alm = tid >> 1, alk = (tid & 1) * 4;
    const int blk = tid >> 5, bln = (tid & 31) * 4;

    const float* Aptr = A + (size_t)(bm + alm) * 4608 + kbase + alk;
    const int bp = bn + bln;                           // column for B loader

    unsigned long long acc[8][4];
#pragma unroll
    for (int i = 0; i < 8; i++)
#pragma unroll
        for (int j = 0; j < 4; j++) acc[i][j] = 0ull;

    float4 av = *(const float4*)Aptr;
    float4 bv = load_feat_quad(kbase + blk, bp);

    for (int k0 = 0; k0 < ksplit; k0 += 8) {
        As[alk + 0][alm] = av.x; As[alk + 1][alm] = av.y;
        As[alk + 2][alm] = av.z; As[alk + 3][alm] = av.w;
        *(float4*)&Bs[blk][bln] = bv;
        __syncthreads();

        if (k0 + 8 < ksplit) {
            av = *(const float4*)(Aptr + k0 + 8);
            bv = load_feat_quad(kbase + k0 + 8 + blk, bp);
        }

#pragma unroll
        for (int k = 0; k < 8; k++) {
            float4 a0 = *(const float4*)&As[k][ty * 4];
            float4 a1 = *(const float4*)&As[k][ty * 4 + 64];
            float4 b0 = *(const float4*)&Bs[k][tx * 4];
            float4 b1 = *(const float4*)&Bs[k][tx * 4 + 64];
            unsigned long long bb[4] = {
                pack2(b0.x, b0.y), pack2(b0.z, b0.w),
                pack2(b1.x, b1.y), pack2(b1.z, b1.w)
            };
            float a[8] = {a0.x, a0.y, a0.z, a0.w, a1.x, a1.y, a1.z, a1.w};
#pragma unroll
            for (int i = 0; i < 8; i++) {
                unsigned long long ad = pack2(a[i], a[i]);
#pragma unroll
                for (int j = 0; j < 4; j++)
                    ffma2(acc[i][j], ad, bb[j]);
            }
        }
        __syncthreads();
    }

    float* Pp = P + (size_t)s * 512 * 1024;
#pragma unroll
    for (int ih = 0; ih < 2; ih++)
#pragma unroll
        for (int r = 0; r < 4; r++) {
            int i = ih * 4 + r;
            int m = bm + ih * 64 + ty * 4 + r;
            float2 p0 = unpack2(acc[i][0]), p1 = unpack2(acc[i][1]);
            float2 p2 = unpack2(acc[i][2]), p3 = unpack2(acc[i][3]);
            *(float4*)(Pp + (size_t)m * 1024 + bn + tx * 4)      = make_float4(p0.x, p0.y, p1.x, p1.y);
            *(float4*)(Pp + (size_t)m * 1024 + bn + tx * 4 + 64) = make_float4(p2.x, p2.y, p3.x, p3.y);
        }
}

// ---------------- deterministic split-K reduce (+bias+relu) ----------------
__global__ void reduce_k(const float* __restrict__ P, float* __restrict__ C,
                         const float* __restrict__ bias, int S, int relu)
{
    int idx = blockIdx.x * blockDim.x + threadIdx.x;   // 131072 threads (float4)
    int m = idx >> 8, n4 = (idx & 255) * 4;
    float4 acc = make_float4(0.f, 0.f, 0.f, 0.f);
    for (int s = 0; s < S; s++) {                      // fixed order
        float4 v = *(const float4*)(P + ((size_t)s * 512 + m) * 1024 + n4);
        acc.x += v.x; acc.y += v.y; acc.z += v.z; acc.w += v.w;
    }
    float bb = bias[m];
    acc.x += bb; acc.y += bb; acc.z += bb; acc.w += bb;
    if (relu) {
        acc.x = fmaxf(acc.x, 0.f); acc.y = fmaxf(acc.y, 0.f);
        acc.z = fmaxf(acc.z, 0.f); acc.w = fmaxf(acc.w, 0.f);
    }
    *(float4*)(C + (size_t)m * 1024 + n4) = acc;
}

// ---------------- stage head weights into one contiguous matrix ----------------
__global__ void copy_wh_k(const float* __restrict__ wc, const float* __restrict__ bc,
                          const float* __restrict__ wb, const float* __restrict__ bb2)
{
    int i = blockIdx.x * blockDim.x + threadIdx.x;     // 23040 threads
    if (i < 9 * 512)       g_wh[i] = wc[9 * 512 + i];          // cls ch 9..17
    else if (i < 45 * 512) g_wh[i] = wb[i - 9 * 512];          // box ch 0..35
    if (i < 9)             g_bh[i] = bc[9 + i];
    else if (i < 45)       g_bh[i] = bb2[i - 9];
}

// ---------------- small GEMM for heads (M<=64): C[M][1024]=A[M][K]xB ----------------
__global__ void gemm_k(const float* __restrict__ A, const float* __restrict__ B,
                       float* __restrict__ C, int M, int K,
                       const float* __restrict__ bias)
{
    __shared__ float As[16][68];
    __shared__ float Bs[16][64];

    const int bn  = blockIdx.x * 64;
    const int tid = threadIdx.x;
    const int tx  = tid & 15, ty = tid >> 4;
    const int lm  = tid >> 2, lkq = (tid & 3) * 4;
    const int lkb = tid >> 4, ln4 = (tid & 15) * 4;

    float acc[4][4] = {};

    float4 av = make_float4(0.f, 0.f, 0.f, 0.f);
    if (lm < M) av = *(const float4*)(A + (size_t)lm * K + lkq);
    float4 bv = *(const float4*)(B + (size_t)lkb * 1024 + bn + ln4);

    for (int k0 = 0; k0 < K; k0 += 16) {
        As[lkq + 0][lm] = av.x; As[lkq + 1][lm] = av.y;
        As[lkq + 2][lm] = av.z; As[lkq + 3][lm] = av.w;
        *(float4*)&Bs[lkb][ln4] = bv;
        __syncthreads();

        int kn = k0 + 16;
        if (kn < K) {
            av = make_float4(0.f, 0.f, 0.f, 0.f);
            if (lm < M) av = *(const float4*)(A + (size_t)lm * K + kn + lkq);
            bv = *(const float4*)(B + (size_t)(kn + lkb) * 1024 + bn + ln4);
        }

#pragma unroll
        for (int k = 0; k < 16; k++) {
            float4 a = *(const float4*)&As[k][ty * 4];
            float4 b = *(const float4*)&Bs[k][tx * 4];
            acc[0][0] += a.x * b.x; acc[0][1] += a.x * b.y; acc[0][2] += a.x * b.z; acc[0][3] += a.x * b.w;
            acc[1][0] += a.y * b.x; acc[1][1] += a.y * b.y; acc[1][2] += a.y * b.z; acc[1][3] += a.y * b.w;
            acc[2][0] += a.z * b.x; acc[2][1] += a.z * b.y; acc[2][2] += a.z * b.z; acc[2][3] += a.z * b.w;
            acc[3][0] += a.w * b.x; acc[3][1] += a.w * b.y; acc[3][2] += a.w * b.z; acc[3][3] += a.w * b.w;
        }
        __syncthreads();
    }

#pragma unroll
    for (int r = 0; r < 4; r++) {
        int m = ty * 4 + r;
        if (m < M) {
            float bb = bias[m];
            float4 o = make_float4(acc[r][0] + bb, acc[r][1] + bb, acc[r][2] + bb, acc[r][3] + bb);
            *(float4*)(C + (size_t)m * 1024 + bn + tx * 4) = o;
        }
    }
}

// ---------------- decode proposals + build sort keys (unique keys) ----------------
__global__ void decode_k(const float* __restrict__ anchors)
{
    int i = blockIdx.x * blockDim.x + threadIdx.x;     // 16384 threads
    if (i >= NANCH) {
        if (i < NSORT) g_keys[i] = (0xFFFFFFFFull << 32) | (unsigned)i;  // unique pad
        return;
    }

    int p = i / 9, k = i - p * 9;
    float s  = g_head[k * 1024 + p];
    float d0 = g_head[(9 + k * 4 + 0) * 1024 + p];
    float d1 = g_head[(9 + k * 4 + 1) * 1024 + p];
    float d2 = g_head[(9 + k * 4 + 2) * 1024 + p];
    float d3 = g_head[(9 + k * 4 + 3) * 1024 + p];

    const float* a = anchors + (size_t)i * 4;
    float ax1 = a[0], ay1 = a[1], ax2 = a[2], ay2 = a[3];
    float wa = ax2 - ax1, ha = ay2 - ay1;
    float cxa = ax1 + 0.5f * wa, cya = ay1 + 0.5f * ha;
    float dw = fminf(fmaxf(d2, -4.f), 4.f);
    float dh = fminf(fmaxf(d3, -4.f), 4.f);
    float cx = cxa + d0 * wa, cy = cya + d1 * ha;
    float w  = wa * expf(dw), h = ha * expf(dh);
    float x1 = fmaxf(cx - 0.5f * w, 0.f);
    float y1 = fmaxf(cy - 0.5f * h, 0.f);
    float x2 = fminf(cx + 0.5f * w, 511.f);
    float y2 = fminf(cy + 0.5f * h, 511.f);
    g_prop[i] = make_float4(x1, y1, x2, y2);

    unsigned b   = __float_as_uint(s);
    unsigned asc = (b & 0x80000000u) ? ~b : (b | 0x80000000u);
    unsigned dsc = ~asc;
    g_keys[i] = ((unsigned long long)dsc << 32) | (unsigned)i;
}

// ---------------- stage A: 16 blocks each bitonic-sort 1024 keys ----------------
__global__ void sort1_k()
{
    __shared__ unsigned long long sk[1024];
    int base = blockIdx.x << 10, t = threadIdx.x;      // 512 threads
    sk[t]       = g_keys[base + t];
    sk[t + 512] = g_keys[base + t + 512];
    __syncthreads();
    for (int k = 2; k <= 1024; k <<= 1) {
        for (int j = k >> 1; j > 0; j >>= 1) {
            for (int e = t; e < 1024; e += 512) {
                int ixj = e ^ j;
                if (ixj > e) {
                    unsigned long long x = sk[e], y = sk[ixj];
                    bool up = ((e & k) == 0);
                    if (up ? (x > y) : (x < y)) { sk[e] = y; sk[ixj] = x; }
                }
            }
            __syncthreads();
        }
    }
    g_keys[base + t]       = sk[t];
    g_keys[base + t + 512] = sk[t + 512];
}

// ---------------- stage B: rank-merge pairs of sorted runs of length L ----------------
__global__ void merge_k(const unsigned long long* __restrict__ src,
                        unsigned long long* __restrict__ dst, int L)
{
    int i = blockIdx.x * blockDim.x + threadIdx.x;     // 16384 threads
    int pair = i / (2 * L);
    int base = pair * 2 * L;
    int r = i - base;
    unsigned long long v = src[base + r];
    const unsigned long long* other;
    int myidx;
    if (r < L) { other = src + base + L; myidx = r; }
    else       { other = src + base;     myidx = r - L; }
    int lo = 0, hi = L;                                // count other < v (keys unique)
    while (lo < hi) {
        int mid = (lo + hi) >> 1;
        if (other[mid] < v) lo = mid + 1; else hi = mid;
    }
    dst[base + myidx + lo] = v;
}

// ---------------- gather sorted boxes ----------------
__global__ void gather_k()
{
    int i = blockIdx.x * blockDim.x + threadIdx.x;
    if (i < NANCH) {
        int idx = (int)(g_keys[i] & 0xFFFFFFFFull);
        g_boxes[i] = g_prop[idx];
    }
}

// ---------------- NMS bitmask (upper triangle only; lower is never read) ----------------
__global__ void nms_mask_k()                           // grid (144, 36), 256 threads
{
    __shared__ float4 cb[64];
    int bx = blockIdx.x;                               // col block (64 wide)
    int t = threadIdx.x;
    int i = blockIdx.y * 256 + t;                      // row
    if (t < 64) cb[t] = g_boxes[bx * 64 + t];
    __syncthreads();

    if (bx < (i >> 6)) return;                         // entire word is j<i: never read

    float4 b  = g_boxes[i];
    float  ai = (b.z - b.x) * (b.w - b.y);
    unsigned long long m = 0ull;
#pragma unroll 4
    for (int jj = 0; jj < 64; jj++) {
        int j = bx * 64 + jj;
        if (j > i) {
            float4 c  = cb[jj];
            float  aj = (c.z - c.x) * (c.w - c.y);
            float iw = fmaxf(fminf(b.z, c.z) - fmaxf(b.x, c.x), 0.f);
            float ih = fmaxf(fminf(b.w, c.w) - fmaxf(b.y, c.y), 0.f);
            float inter = iw * ih;
            float iou = inter / (ai + aj - inter + 1e-9f);
            if (iou > IOU_THR) m |= (1ull << jj);
        }
    }
    g_mask[(size_t)i * NWORDS + bx] = m;
}

// ---------------- chunked greedy NMS reduce (exact serial semantics) ----------------
__global__ void nms_reduce_k(float* __restrict__ out)
{
    __shared__ unsigned long long remv[NWORDS];
    __shared__ unsigned long long keepw[NWORDS];
    __shared__ unsigned long long diag[2][64];
    __shared__ int chunkj[64];
    __shared__ int sel[TOPK];
    __shared__ int s_cnt, s_ccnt, s_done;

    int t = threadIdx.x;                               // 192 threads
    if (t < NWORDS) { remv[t] = 0ull; keepw[t] = 0ull; }
    if (t == 0) { s_cnt = 0; s_done = 0; }
    if (t < 64) diag[0][t] = g_mask[(size_t)t * NWORDS + 0];   // chunk 0 diagonal
    __syncthreads();

    for (int c = 0; c < NWORDS; c++) {
        int buf = c & 1;
        if (t == 0) {
            unsigned long long w  = remv[c];
            unsigned long long kw = 0ull;
            int cc = 0;
            int cnt = s_cnt;
            for (int j = 0; j < 64; j++) {
                if (!((w >> j) & 1ull)) {
                    sel[cnt++] = c * 64 + j;
                    kw |= 1ull << j;
                    chunkj[cc++] = j;
                    if (cnt >= TOPK) break;            // later decisions can't change prefix
                    w |= diag[buf][j];                 // intra-chunk suppression
                }
            }
            keepw[c] = kw;
            s_cnt = cnt;
            s_ccnt = cc;
            if (cnt >= TOPK) s_done = 1;
        }
        __syncthreads();
        if (s_done) break;

        // prefetch next chunk's diagonal block (warps 2-3)
        if (t >= 64 && t < 128 && c + 1 < NWORDS) {
            int tt = t - 64;
            diag[buf ^ 1][tt] =
                g_mask[(size_t)((c + 1) * 64 + tt) * NWORDS + (c + 1)];
        }

        // batched suppression: OR accepted rows into future remv words
        if (t < NWORDS && t > c) {
            unsigned long long r = remv[t];
            int cc = s_ccnt;
            for (int q = 0; q < cc; q++)               // independent loads (MLP)
                r |= g_mask[(size_t)(c * 64 + chunkj[q]) * NWORDS + t];
            remv[t] = r;
        }
        __syncthreads();
    }
    __syncthreads();

    // fewer than 300 kept: stable argsort(~keep) appends suppressed in index order
    if (t == 0 && s_cnt < TOPK) {
        int cnt = s_cnt;
        for (int i = 0; i < NANCH && cnt < TOPK; i++)
            if (!((keepw[i >> 6] >> (i & 63)) & 1ull)) sel[cnt++] = i;
        s_cnt = cnt;
    }
    __syncthreads();

    for (int s = t; s < TOPK; s += blockDim.x) {
        float4 b = g_boxes[sel[s]];
        out[s * 4 + 0] = b.x; out[s * 4 + 1] = b.y;
        out[s * 4 + 2] = b.z; out[s * 4 + 3] = b.w;
    }
}

// ---------------- launch ----------------
extern "C" void kernel_launch(void* const* d_in, const int* in_sizes, int n_in,
                              void* d_out, int out_size)
{
    const float* img     = (const float*)d_in[0];
    const float* anchors = (const float*)d_in[1];
    const float* w_bb    = (const float*)d_in[2];
    const float* b_bb    = (const float*)d_in[3];
    const float* w_rpn   = (const float*)d_in[4];
    const float* b_rpn   = (const float*)d_in[5];
    const float* w_cls   = (const float*)d_in[6];
    const float* b_cls   = (const float*)d_in[7];
    const float* w_box   = (const float*)d_in[8];
    const float* b_box   = (const float*)d_in[9];
    float* out = (float*)d_out;

    float *col1, *feat, *hid, *head, *part, *wh, *bh;
    unsigned long long *keys, *keys2;
    cudaGetSymbolAddress((void**)&col1,  g_col1);
    cudaGetSymbolAddress((void**)&feat,  g_feat);
    cudaGetSymbolAddress((void**)&hid,   g_hid);
    cudaGetSymbolAddress((void**)&head,  g_head);
    cudaGetSymbolAddress((void**)&part,  g_part);
    cudaGetSymbolAddress((void**)&wh,    g_wh);
    cudaGetSymbolAddress((void**)&bh,    g_bh);
    cudaGetSymbolAddress((void**)&keys,  g_keys);
    cudaGetSymbolAddress((void**)&keys2, g_keys2);

    // backbone conv: split-K 4 (K=768, ksplit=192)
    im2col1_k<<<3072, 256>>>(img);                                 // #1
    gemm128_k<<<dim3(8, 4, 4), 256>>>(w_bb, col1, part, 768, 192); // #2
    reduce_k<<<512, 256>>>(part, feat, b_bb, 4, 1);                // #3

    // rpn conv with fused im2col: split-K 8 (K=4608, ksplit=576)  -> profiled launch #4
    gemm128rpn_k<<<dim3(8, 4, 8), 256>>>(w_rpn, part, 576);        // #4
    reduce_k<<<512, 256>>>(part, hid, b_rpn, 8, 1);                // #5

    // heads: stage weights, one 45-row GEMM
    copy_wh_k<<<90, 256>>>(w_cls, b_cls, w_box, b_box);            // #6
    gemm_k<<<16, 256>>>(wh, hid, head, 45, 512, bh);               // #7

    // decode + keys
    decode_k<<<64, 256>>>(anchors);

    // sort: 16 local bitonic sorts, then 4 rank-merge rounds
    sort1_k<<<16, 512>>>();
    merge_k<<<64, 256>>>(keys,  keys2, 1024);
    merge_k<<<64, 256>>>(keys2, keys,  2048);
    merge_k<<<64, 256>>>(keys,  keys2, 4096);
    merge_k<<<64, 256>>>(keys2, keys,  8192);

    gather_k<<<36, 256>>>();

    // NMS
    nms_mask_k<<<dim3(NWORDS, 36), 256>>>();
    nms_reduce_k<<<1, 192>>>(out);
}

// round 11
// speedup vs baseline: 2.1903x; 1.0393x over previous
#include <cuda_runtime.h>
#include <cstdint>

// ---------------- problem constants ----------------
#define NANCH   9216            // 1024*9
#define NWORDS  144             // 9216/64
#define IOU_THR 0.7f
#define TOPK    300

typedef unsigned long long u64;

// ---------------- scratch (static __device__, allocation-free) ----------------
__device__ float  g_feat[512 * 1024];          // backbone features      (2 MB)
__device__ float  g_hid [512 * 1024];          // rpn hidden             (2 MB)
__device__ float  g_part[8 * 512 * 1024];      // split-K partials      (16 MB)
__device__ float  g_head[45 * 1024];           // rows 0..8 cls ch9..17, 9..44 box
__device__ float  g_wh[45 * 512];              // staged head weights
__device__ float  g_bh[45];                    // staged head bias
__device__ float4 g_prop[NANCH];
__device__ u64    g_keys [NANCH];              // 9 sorted runs of 1024
__device__ u64    g_keys2[NANCH];              // fully sorted
__device__ float4 g_boxes[NANCH];
__device__ u64    g_mask[(size_t)NANCH * NWORDS]; // 10.6 MB

// ---------------- packed f32x2 helpers ----------------
__device__ __forceinline__ void ffma2(u64& d, u64 a, u64 b)
{
    asm("fma.rn.f32x2 %0, %1, %2, %0;" : "+l"(d) : "l"(a), "l"(b));
}
__device__ __forceinline__ u64 pack2(float lo, float hi)
{
    u64 r;
    asm("mov.b64 %0, {%1, %2};" : "=l"(r) : "f"(lo), "f"(hi));
    return r;
}
__device__ __forceinline__ float2 unpack2(u64 v)
{
    float2 r;
    asm("mov.b64 {%0, %1}, %2;" : "=f"(r.x), "=f"(r.y) : "l"(v));
    return r;
}

// ---------------- shared GEMM micro-kernel (compute one BK=8 tile) ----------------
#define GEMM_COMPUTE(AsB, BsB)                                                 \
    _Pragma("unroll")                                                          \
    for (int k = 0; k < 8; k++) {                                              \
        float4 a0 = *(const float4*)&AsB[k][ty * 4];                           \
        float4 a1 = *(const float4*)&AsB[k][ty * 4 + 64];                      \
        const u64* Bk = (const u64*)&BsB[k][0];                                \
        u64 bb0 = Bk[tx * 2],      bb1 = Bk[tx * 2 + 1];                       \
        u64 bb2 = Bk[tx * 2 + 32], bb3 = Bk[tx * 2 + 33];                      \
        float a[8] = {a0.x, a0.y, a0.z, a0.w, a1.x, a1.y, a1.z, a1.w};         \
        _Pragma("unroll")                                                      \
        for (int i = 0; i < 8; i++) {                                          \
            u64 ad = pack2(a[i], a[i]);                                        \
            ffma2(acc[i][0], ad, bb0);                                         \
            ffma2(acc[i][1], ad, bb1);                                         \
            ffma2(acc[i][2], ad, bb2);                                         \
            ffma2(acc[i][3], ad, bb3);                                         \
        }                                                                      \
    }

#define GEMM_EPILOGUE(Pdst)                                                    \
    _Pragma("unroll")                                                          \
    for (int ih = 0; ih < 2; ih++)                                             \
        _Pragma("unroll")                                                      \
        for (int r = 0; r < 4; r++) {                                          \
            int i = ih * 4 + r;                                                \
            int m = bm + ih * 64 + ty * 4 + r;                                 \
            float2 p0 = unpack2(acc[i][0]), p1 = unpack2(acc[i][1]);           \
            float2 p2 = unpack2(acc[i][2]), p3 = unpack2(acc[i][3]);           \
            *(float4*)(Pdst + (size_t)m * 1024 + bn + tx * 4)                  \
                = make_float4(p0.x, p0.y, p1.x, p1.y);                         \
            *(float4*)(Pdst + (size_t)m * 1024 + bn + tx * 4 + 64)             \
                = make_float4(p2.x, p2.y, p3.x, p3.y);                         \
        }

// ---------------- backbone GEMM, im2col fused (B from img, quads over k) ----------------
// B[k][p] = img[ci][py*16+ky][px*16+kx], k=ci*256+ky*16+kx, p=py*32+px.
// k quads (k%4==0) are contiguous in img -> LDG.128.
__global__ void __launch_bounds__(256, 2)
gemm128bb_k(const float* __restrict__ A, const float* __restrict__ img,
            float* __restrict__ P, int ksplit)
{
    __shared__ float As[2][8][132];
    __shared__ float Bs[2][8][128];

    const int bn = blockIdx.x * 128;
    const int bm = blockIdx.y * 128;
    const int kbase = blockIdx.z * ksplit;
    const int tid = threadIdx.x;
    const int tx = tid & 15, ty = tid >> 4;
    const int alm = tid >> 1, alk = (tid & 1) * 4;     // A loader
    const int bkq = (tid >> 7) * 4;                    // B loader: k quad base (0 or 4)
    const int bpp = tid & 127;                         // B loader: column

    const float* Aptr = A + (size_t)(bm + alm) * 768 + kbase + alk;
    const int p = bn + bpp, py = p >> 5, px = p & 31;

    u64 acc[8][4];
#pragma unroll
    for (int i = 0; i < 8; i++)
#pragma unroll
        for (int j = 0; j < 4; j++) acc[i][j] = 0ull;

    // prologue loads for tile 0
    float4 av = *(const float4*)Aptr;
    int k = kbase + bkq;
    int ci = k >> 8, r = k & 255, ky = r >> 4, kx = r & 15;
    float4 bv = *(const float4*)(img + ci * 262144 + (py * 16 + ky) * 512 + px * 16 + kx);

    As[0][alk + 0][alm] = av.x; As[0][alk + 1][alm] = av.y;
    As[0][alk + 2][alm] = av.z; As[0][alk + 3][alm] = av.w;
    Bs[0][bkq + 0][bpp] = bv.x; Bs[0][bkq + 1][bpp] = bv.y;
    Bs[0][bkq + 2][bpp] = bv.z; Bs[0][bkq + 3][bpp] = bv.w;
    __syncthreads();

    int buf = 0;
    for (int k0 = 0; k0 < ksplit; k0 += 8) {
        bool more = (k0 + 8 < ksplit);
        if (more) {
            av = *(const float4*)(Aptr + k0 + 8);
            k = kbase + k0 + 8 + bkq;
            ci = k >> 8; r = k & 255; ky = r >> 4; kx = r & 15;
            bv = *(const float4*)(img + ci * 262144 + (py * 16 + ky) * 512 + px * 16 + kx);
        }
        GEMM_COMPUTE(As[buf], Bs[buf])
        if (more) {
            int nb = buf ^ 1;
            As[nb][alk + 0][alm] = av.x; As[nb][alk + 1][alm] = av.y;
            As[nb][alk + 2][alm] = av.z; As[nb][alk + 3][alm] = av.w;
            Bs[nb][bkq + 0][bpp] = bv.x; Bs[nb][bkq + 1][bpp] = bv.y;
            Bs[nb][bkq + 2][bpp] = bv.z; Bs[nb][bkq + 3][bpp] = bv.w;
        }
        __syncthreads();
        buf ^= 1;
    }

    float* Pp = P + (size_t)blockIdx.z * 512 * 1024;
    GEMM_EPILOGUE(Pp)
}

// ---------------- rpn GEMM, im2col fused (B from g_feat, quads over p) ----------------
__device__ __forceinline__ float4 load_feat_quad(int k, int p)
{
    int ci = k / 9, r = k - ci * 9, dy = r / 3, dx = r - dy * 3;
    int py = p >> 5, px = p & 31;                      // px multiple of 4
    int y = py + dy - 1;
    int x0 = px + dx - 1;
    float4 v = make_float4(0.f, 0.f, 0.f, 0.f);
    if ((unsigned)y < 32u) {
        const float* frow = g_feat + ci * 1024 + y * 32 + x0;
        v.x = (x0 >= 0) ? frow[0] : 0.f;
        v.y = frow[1];
        v.z = frow[2];
        v.w = (x0 + 3 <= 31) ? frow[3] : 0.f;
    }
    return v;
}

__global__ void __launch_bounds__(256, 2)
gemm128rpn_k(const float* __restrict__ A, float* __restrict__ P, int ksplit)
{
    __shared__ float As[2][8][132];
    __shared__ float Bs[2][8][128];

    const int bn = blockIdx.x * 128;
    const int bm = blockIdx.y * 128;
    const int kbase = blockIdx.z * ksplit;
    const int tid = threadIdx.x;
    const int tx = tid & 15, ty = tid >> 4;
    const int alm = tid >> 1, alk = (tid & 1) * 4;
    const int blk = tid >> 5, bln = (tid & 31) * 4;

    const float* Aptr = A + (size_t)(bm + alm) * 4608 + kbase + alk;
    const int bp = bn + bln;

    u64 acc[8][4];
#pragma unroll
    for (int i = 0; i < 8; i++)
#pragma unroll
        for (int j = 0; j < 4; j++) acc[i][j] = 0ull;

    float4 av = *(const float4*)Aptr;
    float4 bv = load_feat_quad(kbase + blk, bp);

    As[0][alk + 0][alm] = av.x; As[0][alk + 1][alm] = av.y;
    As[0][alk + 2][alm] = av.z; As[0][alk + 3][alm] = av.w;
    *(float4*)&Bs[0][blk][bln] = bv;
    __syncthreads();

    int buf = 0;
    for (int k0 = 0; k0 < ksplit; k0 += 8) {
        bool more = (k0 + 8 < ksplit);
        if (more) {
            av = *(const float4*)(Aptr + k0 + 8);
            bv = load_feat_quad(kbase + k0 + 8 + blk, bp);
        }
        GEMM_COMPUTE(As[buf], Bs[buf])
        if (more) {
            int nb = buf ^ 1;
            As[nb][alk + 0][alm] = av.x; As[nb][alk + 1][alm] = av.y;
            As[nb][alk + 2][alm] = av.z; As[nb][alk + 3][alm] = av.w;
            *(float4*)&Bs[nb][blk][bln] = bv;
        }
        __syncthreads();
        buf ^= 1;
    }

    float* Pp = P + (size_t)blockIdx.z * 512 * 1024;
    GEMM_EPILOGUE(Pp)
}

// ---------------- deterministic split-K reduce (+bias+relu) ----------------
__global__ void reduce_k(const float* __restrict__ P, float* __restrict__ C,
                         const float* __restrict__ bias, int S, int relu)
{
    int idx = blockIdx.x * blockDim.x + threadIdx.x;   // 131072 threads (float4)
    int m = idx >> 8, n4 = (idx & 255) * 4;
    float4 acc = make_float4(0.f, 0.f, 0.f, 0.f);
    for (int s = 0; s < S; s++) {                      // fixed order
        float4 v = *(const float4*)(P + ((size_t)s * 512 + m) * 1024 + n4);
        acc.x += v.x; acc.y += v.y; acc.z += v.z; acc.w += v.w;
    }
    float bb = bias[m];
    acc.x += bb; acc.y += bb; acc.z += bb; acc.w += bb;
    if (relu) {
        acc.x = fmaxf(acc.x, 0.f); acc.y = fmaxf(acc.y, 0.f);
        acc.z = fmaxf(acc.z, 0.f); acc.w = fmaxf(acc.w, 0.f);
    }
    *(float4*)(C + (size_t)m * 1024 + n4) = acc;
}

// ---------------- stage head weights into one contiguous matrix ----------------
__global__ void copy_wh_k(const float* __restrict__ wc, const float* __restrict__ bc,
                          const float* __restrict__ wb, const float* __restrict__ bb2)
{
    int i = blockIdx.x * blockDim.x + threadIdx.x;     // 23040 threads
    if (i < 9 * 512)       g_wh[i] = wc[9 * 512 + i];          // cls ch 9..17
    else if (i < 45 * 512) g_wh[i] = wb[i - 9 * 512];          // box ch 0..35
    if (i < 9)             g_bh[i] = bc[9 + i];
    else if (i < 45)       g_bh[i] = bb2[i - 9];
}

// ---------------- small GEMM for heads: C[45][1024] = wh x hid ----------------
__global__ void gemm_k(const float* __restrict__ A, const float* __restrict__ B,
                       float* __restrict__ C, int M, int K,
                       const float* __restrict__ bias)
{
    __shared__ float As[16][68];
    __shared__ float Bs[16][64];

    const int bn  = blockIdx.x * 64;
    const int tid = threadIdx.x;
    const int tx  = tid & 15, ty = tid >> 4;
    const int lm  = tid >> 2, lkq = (tid & 3) * 4;
    const int lkb = tid >> 4, ln4 = (tid & 15) * 4;

    float acc[4][4] = {};

    float4 av = make_float4(0.f, 0.f, 0.f, 0.f);
    if (lm < M) av = *(const float4*)(A + (size_t)lm * K + lkq);
    float4 bv = *(const float4*)(B + (size_t)lkb * 1024 + bn + ln4);

    for (int k0 = 0; k0 < K; k0 += 16) {
        As[lkq + 0][lm] = av.x; As[lkq + 1][lm] = av.y;
        As[lkq + 2][lm] = av.z; As[lkq + 3][lm] = av.w;
        *(float4*)&Bs[lkb][ln4] = bv;
        __syncthreads();

        int kn = k0 + 16;
        if (kn < K) {
            av = make_float4(0.f, 0.f, 0.f, 0.f);
            if (lm < M) av = *(const float4*)(A + (size_t)lm * K + kn + lkq);
            bv = *(const float4*)(B + (size_t)(kn + lkb) * 1024 + bn + ln4);
        }

#pragma unroll
        for (int k = 0; k < 16; k++) {
            float4 a = *(const float4*)&As[k][ty * 4];
            float4 b = *(const float4*)&Bs[k][tx * 4];
            acc[0][0] += a.x * b.x; acc[0][1] += a.x * b.y; acc[0][2] += a.x * b.z; acc[0][3] += a.x * b.w;
            acc[1][0] += a.y * b.x; acc[1][1] += a.y * b.y; acc[1][2] += a.y * b.z; acc[1][3] += a.y * b.w;
            acc[2][0] += a.z * b.x; acc[2][1] += a.z * b.y; acc[2][2] += a.z * b.z; acc[2][3] += a.z * b.w;
            acc[3][0] += a.w * b.x; acc[3][1] += a.w * b.y; acc[3][2] += a.w * b.z; acc[3][3] += a.w * b.w;
        }
        __syncthreads();
    }

#pragma unroll
    for (int r = 0; r < 4; r++) {
        int m = ty * 4 + r;
        if (m < M) {
            float bb = bias[m];
            float4 o = make_float4(acc[r][0] + bb, acc[r][1] + bb, acc[r][2] + bb, acc[r][3] + bb);
            *(float4*)(C + (size_t)m * 1024 + bn + tx * 4) = o;
        }
    }
}

// ---------------- decode proposals + build sort keys (unique keys) ----------------
__global__ void decode_k(const float* __restrict__ anchors)
{
    int i = blockIdx.x * blockDim.x + threadIdx.x;     // 9216 threads
    if (i >= NANCH) return;

    int p = i / 9, k = i - p * 9;
    float s  = g_head[k * 1024 + p];
    float d0 = g_head[(9 + k * 4 + 0) * 1024 + p];
    float d1 = g_head[(9 + k * 4 + 1) * 1024 + p];
    float d2 = g_head[(9 + k * 4 + 2) * 1024 + p];
    float d3 = g_head[(9 + k * 4 + 3) * 1024 + p];

    const float* a = anchors + (size_t)i * 4;
    float ax1 = a[0], ay1 = a[1], ax2 = a[2], ay2 = a[3];
    float wa = ax2 - ax1, ha = ay2 - ay1;
    float cxa = ax1 + 0.5f * wa, cya = ay1 + 0.5f * ha;
    float dw = fminf(fmaxf(d2, -4.f), 4.f);
    float dh = fminf(fmaxf(d3, -4.f), 4.f);
    float cx = cxa + d0 * wa, cy = cya + d1 * ha;
    float w  = wa * expf(dw), h = ha * expf(dh);
    float x1 = fmaxf(cx - 0.5f * w, 0.f);
    float y1 = fmaxf(cy - 0.5f * h, 0.f);
    float x2 = fminf(cx + 0.5f * w, 511.f);
    float y2 = fminf(cy + 0.5f * h, 511.f);
    g_prop[i] = make_float4(x1, y1, x2, y2);

    unsigned b   = __float_as_uint(s);
    unsigned asc = (b & 0x80000000u) ? ~b : (b | 0x80000000u);
    unsigned dsc = ~asc;                               // finite score -> dsc <= 0xFFFFFFFE
    g_keys[i] = ((u64)dsc << 32) | (unsigned)i;
}

// ---------------- stage A: 9 blocks each bitonic-sort 1024 keys ----------------
__global__ void sort1_k()
{
    __shared__ u64 sk[1024];
    int base = blockIdx.x << 10, t = threadIdx.x;      // 512 threads
    sk[t]       = g_keys[base + t];
    sk[t + 512] = g_keys[base + t + 512];
    __syncthreads();
    for (int k = 2; k <= 1024; k <<= 1) {
        for (int j = k >> 1; j > 0; j >>= 1) {
            for (int e = t; e < 1024; e += 512) {
                int ixj = e ^ j;
                if (ixj > e) {
                    u64 x = sk[e], y = sk[ixj];
                    bool up = ((e & k) == 0);
                    if (up ? (x > y) : (x < y)) { sk[e] = y; sk[ixj] = x; }
                }
            }
            __syncthreads();
        }
    }
    g_keys[base + t]       = sk[t];
    g_keys[base + t + 512] = sk[t + 512];
}

// ---------------- stage B: single-pass 9-way rank-merge ----------------
// rank(v) = sum over all 9 runs of lower_bound(run, v); keys unique -> bijection.
// 9 independent branchless search chains per thread -> high MLP, L2-resident.
__global__ void merge9_k(const u64* __restrict__ src, u64* __restrict__ dst)
{
    int i = blockIdx.x * blockDim.x + threadIdx.x;     // 9216 threads
    u64 v = src[i];
    int rank = 0;
#pragma unroll
    for (int run = 0; run < 9; run++) {
        const u64* base = src + (run << 10);
        int pos = 0;
#pragma unroll
        for (int w = 512; w >= 1; w >>= 1)
            if (base[pos + w - 1] < v) pos += w;
        if (base[pos] < v) pos++;
        rank += pos;
    }
    dst[rank] = v;
}

// ---------------- gather sorted boxes ----------------
__global__ void gather_k()
{
    int i = blockIdx.x * blockDim.x + threadIdx.x;
    if (i < NANCH) {
        int idx = (int)(g_keys2[i] & 0xFFFFFFFFull);
        g_boxes[i] = g_prop[idx];
    }
}

// ---------------- NMS bitmask (upper triangle only) ----------------
__global__ void nms_mask_k()                           // grid (144, 36), 256 threads
{
    __shared__ float4 cb[64];
    int bx = blockIdx.x;
    int t = threadIdx.x;
    int i = blockIdx.y * 256 + t;
    if (t < 64) cb[t] = g_boxes[bx * 64 + t];
    __syncthreads();

    if (bx < (i >> 6)) return;

    float4 b  = g_boxes[i];
    float  ai = (b.z - b.x) * (b.w - b.y);
    u64 m = 0ull;
#pragma unroll 4
    for (int jj = 0; jj < 64; jj++) {
        int j = bx * 64 + jj;
        if (j > i) {
            float4 c  = cb[jj];
            float  aj = (c.z - c.x) * (c.w - c.y);
            float iw = fmaxf(fminf(b.z, c.z) - fmaxf(b.x, c.x), 0.f);
            float ih = fmaxf(fminf(b.w, c.w) - fmaxf(b.y, c.y), 0.f);
            float inter = iw * ih;
            float iou = inter / (ai + aj - inter + 1e-9f);
            if (iou > IOU_THR) m |= (1ull << jj);
        }
    }
    g_mask[(size_t)i * NWORDS + bx] = m;
}

// ---------------- chunked greedy NMS reduce (exact serial semantics) ----------------
__global__ void nms_reduce_k(float* __restrict__ out)
{
    __shared__ u64 remv[NWORDS];
    __shared__ u64 keepw[NWORDS];
    __shared__ u64 diag[2][64];
    __shared__ int chunkj[64];
    __shared__ int sel[TOPK];
    __shared__ int s_cnt, s_ccnt, s_done;

    int t = threadIdx.x;                               // 192 threads
    if (t < NWORDS) { remv[t] = 0ull; keepw[t] = 0ull; }
    if (t == 0) { s_cnt = 0; s_done = 0; }
    if (t < 64) diag[0][t] = g_mask[(size_t)t * NWORDS + 0];
    __syncthreads();

    for (int c = 0; c < NWORDS; c++) {
        int buf = c & 1;
        if (t == 0) {
            u64 w  = remv[c];
            u64 kw = 0ull;
            int cc = 0;
            int cnt = s_cnt;
            for (int j = 0; j < 64; j++) {
                if (!((w >> j) & 1ull)) {
                    sel[cnt++] = c * 64 + j;
                    kw |= 1ull << j;
                    chunkj[cc++] = j;
                    if (cnt >= TOPK) break;
                    w |= diag[buf][j];
                }
            }
            keepw[c] = kw;
            s_cnt = cnt;
            s_ccnt = cc;
            if (cnt >= TOPK) s_done = 1;
        }
        __syncthreads();
        if (s_done) break;

        if (t >= 64 && t < 128 && c + 1 < NWORDS) {
            int tt = t - 64;
            diag[buf ^ 1][tt] =
                g_mask[(size_t)((c + 1) * 64 + tt) * NWORDS + (c + 1)];
        }

        if (t < NWORDS && t > c) {
            u64 r = remv[t];
            int cc = s_ccnt;
            for (int q = 0; q < cc; q++)
                r |= g_mask[(size_t)(c * 64 + chunkj[q]) * NWORDS + t];
            remv[t] = r;
        }
        __syncthreads();
    }
    __syncthreads();

    if (t == 0 && s_cnt < TOPK) {
        int cnt = s_cnt;
        for (int i = 0; i < NANCH && cnt < TOPK; i++)
            if (!((keepw[i >> 6] >> (i & 63)) & 1ull)) sel[cnt++] = i;
        s_cnt = cnt;
    }
    __syncthreads();

    for (int s = t; s < TOPK; s += blockDim.x) {
        float4 b = g_boxes[sel[s]];
        out[s * 4 + 0] = b.x; out[s * 4 + 1] = b.y;
        out[s * 4 + 2] = b.z; out[s * 4 + 3] = b.w;
    }
}

// ---------------- launch ----------------
extern "C" void kernel_launch(void* const* d_in, const int* in_sizes, int n_in,
                              void* d_out, int out_size)
{
    const float* img     = (const float*)d_in[0];
    const float* anchors = (const float*)d_in[1];
    const float* w_bb    = (const float*)d_in[2];
    const float* b_bb    = (const float*)d_in[3];
    const float* w_rpn   = (const float*)d_in[4];
    const float* b_rpn   = (const float*)d_in[5];
    const float* w_cls   = (const float*)d_in[6];
    const float* b_cls   = (const float*)d_in[7];
    const float* w_box   = (const float*)d_in[8];
    const float* b_box   = (const float*)d_in[9];
    float* out = (float*)d_out;

    float *feat, *hid, *head, *part, *wh, *bh;
    u64 *keys, *keys2;
    cudaGetSymbolAddress((void**)&feat,  g_feat);
    cudaGetSymbolAddress((void**)&hid,   g_hid);
    cudaGetSymbolAddress((void**)&head,  g_head);
    cudaGetSymbolAddress((void**)&part,  g_part);
    cudaGetSymbolAddress((void**)&wh,    g_wh);
    cudaGetSymbolAddress((void**)&bh,    g_bh);
    cudaGetSymbolAddress((void**)&keys,  g_keys);
    cudaGetSymbolAddress((void**)&keys2, g_keys2);

    // backbone conv, im2col fused: split-K 4 (K=768, ksplit=192)
    gemm128bb_k<<<dim3(8, 4, 4), 256>>>(w_bb, img, part, 192);
    reduce_k<<<512, 256>>>(part, feat, b_bb, 4, 1);

    // rpn conv, im2col fused: split-K 8 (K=4608, ksplit=576)
    gemm128rpn_k<<<dim3(8, 4, 8), 256>>>(w_rpn, part, 576);
    reduce_k<<<512, 256>>>(part, hid, b_rpn, 8, 1);

    // heads: stage weights, one 45-row GEMM
    copy_wh_k<<<90, 256>>>(w_cls, b_cls, w_box, b_box);
    gemm_k<<<16, 256>>>(wh, hid, head, 45, 512, bh);

    // decode + keys (real anchors only; pads eliminated)
    decode_k<<<36, 256>>>(anchors);

    // sort: 9 local bitonic sorts, then one 9-way rank-merge
    sort1_k<<<9, 512>>>();
    merge9_k<<<36, 256>>>(keys, keys2);

    gather_k<<<36, 256>>>();

    // NMS
    nms_mask_k<<<dim3(NWORDS, 36), 256>>>();
    nms_reduce_k<<<1, 192>>>(out);
}